// round 14
// baseline (speedup 1.0000x reference)
#include <cuda_runtime.h>
#include <cuda_bf16.h>
#include <cstdint>

#define HDIM   256
#define NSUB   32768
#define NGLOB  65536
#define SSEG   1024
#define ESUB_MAX   262144
#define EGLOB_MAX  1048576
#define CAPS (ESUB_MAX  + 4 * NSUB)
#define CAPG (EGLOB_MAX + 4 * NGLOB)

// ---------------- scratch ----------------
__device__ float g_dis_sub[NSUB];
__device__ float g_dis_glob[NGLOB];
__device__ float g_pooled[SSEG * HDIM];
__device__ float g_cnt[SSEG];
__device__ float g_gemb_part[64 * HDIM];
__device__ int   g_gcnt;

__device__ int g_cntdeg_sub[NSUB];
__device__ int g_cntdeg_glob[NGLOB];
__device__ int g_off_sub[NSUB + 1];
__device__ int g_off_glob[NGLOB + 1];
__device__ int g_cur_sub[NSUB];
__device__ int g_cur_glob[NGLOB];
__device__ int g_bsum_sub[NSUB / 256];
__device__ int g_bsum_glob[NGLOB / 256];
__device__ __align__(16) int g_csr_sub[CAPS];
__device__ __align__(16) int g_csr_glob[CAPG];

__device__ __align__(16) __nv_bfloat16 g_hs_sub [(NSUB  + 1) * HDIM];
__device__ __align__(16) __nv_bfloat16 g_hs_glob[(NGLOB + 1) * HDIM];
__device__ __align__(16) __nv_bfloat16 g_bWt_sub [HDIM * HDIM];
__device__ __align__(16) __nv_bfloat16 g_bWt_glob[HDIM * HDIM];

// ---------------- PTX helpers ----------------
__device__ __forceinline__ void red4(float* p, float x, float y, float z, float w) {
    asm volatile("red.global.add.v4.f32 [%0], {%1, %2, %3, %4};"
                 :: "l"(p), "f"(x), "f"(y), "f"(z), "f"(w) : "memory");
}
__device__ __forceinline__ void cp_async16(uint32_t dst, const void* src) {
    asm volatile("cp.async.cg.shared.global [%0], [%1], 16;" :: "r"(dst), "l"(src) : "memory");
}
__device__ __forceinline__ void cp_commit() {
    asm volatile("cp.async.commit_group;" ::: "memory");
}
template <int N>
__device__ __forceinline__ void cp_wait() {
    asm volatile("cp.async.wait_group %0;" :: "n"(N) : "memory");
}
__device__ __forceinline__ void ldsm_x4(uint32_t& r0, uint32_t& r1, uint32_t& r2, uint32_t& r3,
                                        uint32_t addr) {
    asm volatile("ldmatrix.sync.aligned.m8n8.x4.shared.b16 {%0,%1,%2,%3}, [%4];"
                 : "=r"(r0), "=r"(r1), "=r"(r2), "=r"(r3) : "r"(addr));
}
__device__ __forceinline__ void mma_bf16(float* c, const uint32_t* a, const uint32_t* b) {
    asm volatile(
        "mma.sync.aligned.m16n8k16.row.col.f32.bf16.bf16.f32 "
        "{%0,%1,%2,%3}, {%4,%5,%6,%7}, {%8,%9}, {%0,%1,%2,%3};"
        : "+f"(c[0]), "+f"(c[1]), "+f"(c[2]), "+f"(c[3])
        : "r"(a[0]), "r"(a[1]), "r"(a[2]), "r"(a[3]), "r"(b[0]), "r"(b[1]));
}
__device__ __forceinline__ __nv_bfloat162 badd2(__nv_bfloat162 a, __nv_bfloat162 b) {
    return __hadd2(a, b);
}

// ---------------- combined init (R12) ----------------
__global__ void k_init() {
    int i = blockIdx.x * blockDim.x + threadIdx.x;   // grid covers 262144
    if (i < NGLOB) g_cntdeg_glob[i] = 0;
    if (i < NSUB)  g_cntdeg_sub[i]  = 0;
    if (i < SSEG * HDIM) g_pooled[i] = 0.0f;
    if (i < 64 * HDIM)   g_gemb_part[i] = 0.0f;
    if (i < SSEG)        g_cnt[i] = 0.0f;
    if (i < HDIM) {
        g_hs_sub [NSUB  * HDIM + i] = __float2bfloat16(0.0f);
        g_hs_glob[NGLOB * HDIM + i] = __float2bfloat16(0.0f);
    }
    if (i == 0) g_gcnt = 0;
}

// combined hist: glob edges, sub edges, sub batch counts
__global__ void k_hist_all(const int* __restrict__ ei_glob, int Eg,
                           const int* __restrict__ ei_sub, int Es,
                           const int* __restrict__ batch_sub) {
    int i = blockIdx.x * blockDim.x + threadIdx.x;
    if (i < Eg) {
        atomicAdd(&g_cntdeg_glob[ei_glob[Eg + i]], 1);
    } else if (i < Eg + Es) {
        int j = i - Eg;
        atomicAdd(&g_cntdeg_sub[ei_sub[Es + j]], 1);
    } else if (i < Eg + Es + NSUB) {
        int j = i - Eg - Es;
        atomicAdd(&g_cnt[batch_sub[j]], 1.0f);
    }
}

// ---- scan chain (R12) ----
__global__ void k_scan1_all() {
    __shared__ int sh[8];
    int b = blockIdx.x;
    const int* cnt;
    float* dis;
    int* bsum;
    int bb;
    if (b < 256) { cnt = g_cntdeg_glob; dis = g_dis_glob; bsum = g_bsum_glob; bb = b; }
    else         { cnt = g_cntdeg_sub;  dis = g_dis_sub;  bsum = g_bsum_sub;  bb = b - 256; }
    int i = bb * 256 + threadIdx.x;
    int c = cnt[i];
    dis[i] = rsqrtf((float)c + 1.0f);
    int p = (c + 3) & ~3;
    for (int o = 16; o; o >>= 1) p += __shfl_down_sync(~0u, p, o);
    if ((threadIdx.x & 31) == 0) sh[threadIdx.x >> 5] = p;
    __syncthreads();
    if (threadIdx.x < 8) {
        int v = sh[threadIdx.x];
        for (int o = 4; o; o >>= 1) v += __shfl_down_sync(0xff, v, o);
        if (threadIdx.x == 0) bsum[bb] = v;
    }
}
__global__ void k_scan2_all() {
    __shared__ int sh[256];
    int* bsum = blockIdx.x == 0 ? g_bsum_glob : g_bsum_sub;
    int NB    = blockIdx.x == 0 ? (NGLOB / 256) : (NSUB / 256);
    int t = threadIdx.x;
    int v = (t < NB) ? bsum[t] : 0;
    sh[t] = v;
    __syncthreads();
    for (int d = 1; d < 256; d <<= 1) {
        int u = (t >= d) ? sh[t - d] : 0;
        __syncthreads();
        sh[t] += u;
        __syncthreads();
    }
    if (t < NB) bsum[t] = sh[t] - v;
}
__global__ void k_scan3_all() {
    __shared__ int sh[256];
    int b = blockIdx.x;
    const int* cnt;
    const int* bsum;
    int* off;
    int* cur;
    int bb, N;
    if (b < 256) { cnt = g_cntdeg_glob; bsum = g_bsum_glob; off = g_off_glob; cur = g_cur_glob; bb = b; N = NGLOB; }
    else         { cnt = g_cntdeg_sub;  bsum = g_bsum_sub;  off = g_off_sub;  cur = g_cur_sub;  bb = b - 256; N = NSUB; }
    int t = threadIdx.x;
    int i = bb * 256 + t;
    int c = cnt[i];
    int p = (c + 3) & ~3;
    sh[t] = p;
    __syncthreads();
    for (int d = 1; d < 256; d <<= 1) {
        int u = (t >= d) ? sh[t - d] : 0;
        __syncthreads();
        sh[t] += u;
        __syncthreads();
    }
    int excl = sh[t] - p + bsum[bb];
    off[i] = excl;
    cur[i] = excl;
    if (i == N - 1) off[N] = excl + p;
}
__global__ void k_fill_all(const int* __restrict__ ei_glob, int Eg,
                           const int* __restrict__ ei_sub, int Es) {
    int i = blockIdx.x * blockDim.x + threadIdx.x;
    if (i < Eg) {
        int p = atomicAdd(&g_cur_glob[ei_glob[Eg + i]], 1);
        g_csr_glob[p] = ei_glob[i];
    } else if (i < Eg + Es) {
        int j = i - Eg;
        int p = atomicAdd(&g_cur_sub[ei_sub[Es + j]], 1);
        g_csr_sub[p] = ei_sub[j];
    }
}
__global__ void k_pad_all() {
    int b = blockIdx.x;
    const int* cnt;
    const int* off;
    int* csr;
    int bb, N;
    if (b < 256) { cnt = g_cntdeg_glob; off = g_off_glob; csr = g_csr_glob; bb = b; N = NGLOB; }
    else         { cnt = g_cntdeg_sub;  off = g_off_sub;  csr = g_csr_sub;  bb = b - 256; N = NSUB; }
    int i = bb * 256 + threadIdx.x;
    int c = cnt[i], o = off[i], p = (c + 3) & ~3;
    for (int j = c; j < p; j++) csr[o + j] = N;
}

// ---------------- dual W pack ----------------
__global__ void k_pack_Wt2(const float* __restrict__ Wg, const float* __restrict__ Ws) {
    __shared__ float tile[32][33];
    const float* W = blockIdx.z == 0 ? Wg : Ws;
    __nv_bfloat16* out = blockIdx.z == 0 ? g_bWt_glob : g_bWt_sub;
    int bx = blockIdx.x * 32, by = blockIdx.y * 32;
    int tx = threadIdx.x & 31, ty = threadIdx.x >> 5;
    for (int i = 0; i < 32; i += 8)
        tile[ty + i][tx] = W[(by + ty + i) * HDIM + bx + tx];
    __syncthreads();
    for (int i = 0; i < 32; i += 8)
        out[(bx + ty + i) * HDIM + by + tx] = __float2bfloat16(tile[tx][ty + i]);
}

// ---------------- bf16 mma GEMM, fp32 A in-kernel convert ----------------
// rowdiv: optional per-row divide during convert (fused mean)
// inj:    optional row->node map; epilogue does hs[node] += acc*dis[node] (bf16 RMW)
#define GEMM_SMEM (32768 + 32768 + 32768)
__global__ __launch_bounds__(256, 2) void k_gemm_mma(
    const float* __restrict__ A,
    const __nv_bfloat16* __restrict__ Wt,
    __nv_bfloat16* __restrict__ Hs,
    const float* __restrict__ dis,
    const float* __restrict__ rowdiv,
    const int* __restrict__ inj)
{
    extern __shared__ __align__(16) unsigned char smem[];
    const int tid  = threadIdx.x;
    const int lane = tid & 31, warp = tid >> 5;
    const int wm = warp & 3, wn = warp >> 2;
    const int row0 = blockIdx.x * 128, col0 = blockIdx.y * 128;
    uint32_t sbase = (uint32_t)__cvta_generic_to_shared(smem);
    const uint32_t STG = sbase;
    const uint32_t ABF = sbase + 32768;
    const uint32_t BB  = sbase + 65536;

    float acc[2][8][4];
#pragma unroll
    for (int mt = 0; mt < 2; mt++)
#pragma unroll
        for (int nt = 0; nt < 8; nt++)
#pragma unroll
            for (int i = 0; i < 4; i++) acc[mt][nt][i] = 0.0f;

    auto load_A_stage = [&](int kc) {
#pragma unroll
        for (int i = 0; i < 8; i++) {
            int id = tid + i * 256;
            int r = id >> 4, c4 = id & 15;
            cp_async16(STG + (uint32_t)id * 16,
                       A + (size_t)(row0 + r) * HDIM + kc * 64 + c4 * 4);
        }
    };
    auto load_B = [&](int s, int kc) {
#pragma unroll
        for (int i = 0; i < 4; i++) {
            int id = tid + i * 256;
            int r = id >> 3, c = id & 7;
            cp_async16(BB + s * 16384 + (uint32_t)(r * 128 + ((c ^ (r & 7)) << 4)),
                       Wt + (size_t)(col0 + r) * HDIM + kc * 64 + c * 8);
        }
    };
    auto convert_A = [&](int s) {
#pragma unroll
        for (int i = 0; i < 8; i++) {
            int id = tid + i * 256;
            int r = id >> 4, c4 = id & 15;
            float4 v;
            asm volatile("ld.shared.v4.f32 {%0,%1,%2,%3}, [%4];"
                         : "=f"(v.x), "=f"(v.y), "=f"(v.z), "=f"(v.w)
                         : "r"(STG + (uint32_t)id * 16));
            if (rowdiv) {
                float inv = 1.0f / fmaxf(rowdiv[row0 + r], 1.0f);
                v.x *= inv; v.y *= inv; v.z *= inv; v.w *= inv;
            }
            __nv_bfloat162 lo = __floats2bfloat162_rn(v.x, v.y);
            __nv_bfloat162 hi = __floats2bfloat162_rn(v.z, v.w);
            int cc = c4 >> 1, half = (c4 & 1) * 8;
            uint32_t addr = ABF + s * 16384 +
                            (uint32_t)(r * 128 + ((cc ^ (r & 7)) << 4) + half);
            asm volatile("st.shared.v2.b32 [%0], {%1,%2};"
                         :: "r"(addr),
                            "r"(*reinterpret_cast<uint32_t*>(&lo)),
                            "r"(*reinterpret_cast<uint32_t*>(&hi)));
        }
    };
    auto compute = [&](int s) {
        uint32_t sA = ABF + s * 16384;
        uint32_t sB = BB + s * 16384;
#pragma unroll
        for (int kk = 0; kk < 4; kk++) {
            uint32_t af[2][4];
#pragma unroll
            for (int mt = 0; mt < 2; mt++) {
                int r = wm * 32 + mt * 16 + (lane & 15);
                int c = kk * 2 + (lane >> 4);
                ldsm_x4(af[mt][0], af[mt][1], af[mt][2], af[mt][3],
                        sA + r * 128 + ((c ^ (r & 7)) << 4));
            }
            uint32_t bf[8][2];
#pragma unroll
            for (int p = 0; p < 4; p++) {
                int r = wn * 64 + p * 16 + ((lane >> 4) << 3) + (lane & 7);
                int c = kk * 2 + ((lane >> 3) & 1);
                ldsm_x4(bf[2 * p][0], bf[2 * p][1], bf[2 * p + 1][0], bf[2 * p + 1][1],
                        sB + r * 128 + ((c ^ (r & 7)) << 4));
            }
#pragma unroll
            for (int mt = 0; mt < 2; mt++)
#pragma unroll
                for (int nt = 0; nt < 8; nt++)
                    mma_bf16(acc[mt][nt], af[mt], bf[nt]);
        }
    };

    load_A_stage(0);
    load_B(0, 0);
    cp_commit();
    cp_wait<0>();
    __syncthreads();
    convert_A(0);
    __syncthreads();

    int s = 0;
#pragma unroll 1
    for (int kc = 0; kc < 4; kc++) {
        if (kc < 3) {
            load_A_stage(kc + 1);
            load_B(s ^ 1, kc + 1);
            cp_commit();
        }
        compute(s);
        if (kc < 3) {
            cp_wait<0>();
            __syncthreads();
            convert_A(s ^ 1);
            __syncthreads();
            s ^= 1;
        }
    }

    const int g = lane >> 2, t4 = lane & 3;
#pragma unroll
    for (int mt = 0; mt < 2; mt++) {
        int r_lo = row0 + wm * 32 + mt * 16 + g;
        int r_hi = r_lo + 8;
        if (inj) {
            // inject mode: hs[node] += acc * dis[node]  (rows unique -> race-free)
            int n_lo = inj[r_lo], n_hi = inj[r_hi];
            float dlo = dis[n_lo], dhi = dis[n_hi];
#pragma unroll
            for (int nt = 0; nt < 8; nt++) {
                int col = col0 + wn * 64 + nt * 8 + 2 * t4;
                __nv_bfloat162* plo = (__nv_bfloat162*)&Hs[(size_t)n_lo * HDIM + col];
                __nv_bfloat162* phi = (__nv_bfloat162*)&Hs[(size_t)n_hi * HDIM + col];
                float2 hlo = __bfloat1622float2(*plo);
                float2 hhi = __bfloat1622float2(*phi);
                *plo = __floats2bfloat162_rn(fmaf(acc[mt][nt][0], dlo, hlo.x),
                                             fmaf(acc[mt][nt][1], dlo, hlo.y));
                *phi = __floats2bfloat162_rn(fmaf(acc[mt][nt][2], dhi, hhi.x),
                                             fmaf(acc[mt][nt][3], dhi, hhi.y));
            }
        } else {
            float dlo = dis[r_lo], dhi = dis[r_hi];
#pragma unroll
            for (int nt = 0; nt < 8; nt++) {
                int col = col0 + wn * 64 + nt * 8 + 2 * t4;
                __nv_bfloat162 lo = __floats2bfloat162_rn(acc[mt][nt][0] * dlo,
                                                          acc[mt][nt][1] * dlo);
                __nv_bfloat162 hi = __floats2bfloat162_rn(acc[mt][nt][2] * dhi,
                                                          acc[mt][nt][3] * dhi);
                *(__nv_bfloat162*)&Hs[(size_t)r_lo * HDIM + col] = lo;
                *(__nv_bfloat162*)&Hs[(size_t)r_hi * HDIM + col] = hi;
            }
        }
    }
}

// ---------------- CSR gather + fused epilogues (pad-4, int4 indices) ----------
__global__ __launch_bounds__(256) void k_gather_sub(
    const int* __restrict__ batch, const float* __restrict__ bias)
{
    const int lane = threadIdx.x & 31, grp = threadIdx.x >> 5;
    const uint4* H = (const uint4*)g_hs_sub;
    float4 b0 = ((const float4*)bias)[lane * 2];
    float4 b1 = ((const float4*)bias)[lane * 2 + 1];
#pragma unroll 1
    for (int it = 0; it < 4; it++) {
        int n = blockIdx.x * 32 + it * 8 + grp;
        int o0 = g_off_sub[n] >> 2, o1 = g_off_sub[n + 1] >> 2;
        uint4 a = H[(size_t)n * 32 + lane];
        __nv_bfloat162 A0 = *(__nv_bfloat162*)&a.x, A1 = *(__nv_bfloat162*)&a.y,
                       A2 = *(__nv_bfloat162*)&a.z, A3 = *(__nv_bfloat162*)&a.w;
#pragma unroll 1
        for (int k = o0; k < o1; k++) {
            int4 s4 = ((const int4*)g_csr_sub)[k];
            uint4 v;
            v = H[(size_t)s4.x * 32 + lane];
            A0 = badd2(A0, *(__nv_bfloat162*)&v.x); A1 = badd2(A1, *(__nv_bfloat162*)&v.y);
            A2 = badd2(A2, *(__nv_bfloat162*)&v.z); A3 = badd2(A3, *(__nv_bfloat162*)&v.w);
            v = H[(size_t)s4.y * 32 + lane];
            A0 = badd2(A0, *(__nv_bfloat162*)&v.x); A1 = badd2(A1, *(__nv_bfloat162*)&v.y);
            A2 = badd2(A2, *(__nv_bfloat162*)&v.z); A3 = badd2(A3, *(__nv_bfloat162*)&v.w);
            v = H[(size_t)s4.z * 32 + lane];
            A0 = badd2(A0, *(__nv_bfloat162*)&v.x); A1 = badd2(A1, *(__nv_bfloat162*)&v.y);
            A2 = badd2(A2, *(__nv_bfloat162*)&v.z); A3 = badd2(A3, *(__nv_bfloat162*)&v.w);
            v = H[(size_t)s4.w * 32 + lane];
            A0 = badd2(A0, *(__nv_bfloat162*)&v.x); A1 = badd2(A1, *(__nv_bfloat162*)&v.y);
            A2 = badd2(A2, *(__nv_bfloat162*)&v.z); A3 = badd2(A3, *(__nv_bfloat162*)&v.w);
        }
        float d = g_dis_sub[n];
        float2 f0 = __bfloat1622float2(A0), f1 = __bfloat1622float2(A1);
        float2 f2 = __bfloat1622float2(A2), f3 = __bfloat1622float2(A3);
        float* dst = g_pooled + (size_t)batch[n] * HDIM + lane * 8;
        red4(dst,
             fmaxf(fmaf(f0.x, d, b0.x), 0.0f), fmaxf(fmaf(f0.y, d, b0.y), 0.0f),
             fmaxf(fmaf(f1.x, d, b0.z), 0.0f), fmaxf(fmaf(f1.y, d, b0.w), 0.0f));
        red4(dst + 4,
             fmaxf(fmaf(f2.x, d, b1.x), 0.0f), fmaxf(fmaf(f2.y, d, b1.y), 0.0f),
             fmaxf(fmaf(f3.x, d, b1.z), 0.0f), fmaxf(fmaf(f3.y, d, b1.w), 0.0f));
    }
}

__global__ __launch_bounds__(256) void k_gather_glob(
    const int* __restrict__ batch, const float* __restrict__ bias)
{
    const int lane = threadIdx.x & 31, grp = threadIdx.x >> 5;
    const uint4* H = (const uint4*)g_hs_glob;
    float4 b0 = ((const float4*)bias)[lane * 2];
    float4 b1 = ((const float4*)bias)[lane * 2 + 1];
    float r0 = 0, r1 = 0, r2 = 0, r3 = 0, r4 = 0, r5 = 0, r6 = 0, r7 = 0;
    int cloc = 0;
#pragma unroll 1
    for (int it = 0; it < 4; it++) {
        int n = blockIdx.x * 32 + it * 8 + grp;
        int o0 = g_off_glob[n] >> 2, o1 = g_off_glob[n + 1] >> 2;
        uint4 a = H[(size_t)n * 32 + lane];
        __nv_bfloat162 A0 = *(__nv_bfloat162*)&a.x, A1 = *(__nv_bfloat162*)&a.y,
                       A2 = *(__nv_bfloat162*)&a.z, A3 = *(__nv_bfloat162*)&a.w;
#pragma unroll 1
        for (int k = o0; k < o1; k++) {
            int4 s4 = ((const int4*)g_csr_glob)[k];
            uint4 v;
            v = H[(size_t)s4.x * 32 + lane];
            A0 = badd2(A0, *(__nv_bfloat162*)&v.x); A1 = badd2(A1, *(__nv_bfloat162*)&v.y);
            A2 = badd2(A2, *(__nv_bfloat162*)&v.z); A3 = badd2(A3, *(__nv_bfloat162*)&v.w);
            v = H[(size_t)s4.y * 32 + lane];
            A0 = badd2(A0, *(__nv_bfloat162*)&v.x); A1 = badd2(A1, *(__nv_bfloat162*)&v.y);
            A2 = badd2(A2, *(__nv_bfloat162*)&v.z); A3 = badd2(A3, *(__nv_bfloat162*)&v.w);
            v = H[(size_t)s4.z * 32 + lane];
            A0 = badd2(A0, *(__nv_bfloat162*)&v.x); A1 = badd2(A1, *(__nv_bfloat162*)&v.y);
            A2 = badd2(A2, *(__nv_bfloat162*)&v.z); A3 = badd2(A3, *(__nv_bfloat162*)&v.w);
            v = H[(size_t)s4.w * 32 + lane];
            A0 = badd2(A0, *(__nv_bfloat162*)&v.x); A1 = badd2(A1, *(__nv_bfloat162*)&v.y);
            A2 = badd2(A2, *(__nv_bfloat162*)&v.z); A3 = badd2(A3, *(__nv_bfloat162*)&v.w);
        }
        if (batch[n] == 0) {
            float d = g_dis_glob[n];
            float2 f0 = __bfloat1622float2(A0), f1 = __bfloat1622float2(A1);
            float2 f2 = __bfloat1622float2(A2), f3 = __bfloat1622float2(A3);
            r0 += fmaxf(fmaf(f0.x, d, b0.x), 0.0f);
            r1 += fmaxf(fmaf(f0.y, d, b0.y), 0.0f);
            r2 += fmaxf(fmaf(f1.x, d, b0.z), 0.0f);
            r3 += fmaxf(fmaf(f1.y, d, b0.w), 0.0f);
            r4 += fmaxf(fmaf(f2.x, d, b1.x), 0.0f);
            r5 += fmaxf(fmaf(f2.y, d, b1.y), 0.0f);
            r6 += fmaxf(fmaf(f3.x, d, b1.z), 0.0f);
            r7 += fmaxf(fmaf(f3.y, d, b1.w), 0.0f);
            cloc++;
        }
    }
    float* dst = g_gemb_part + (size_t)(blockIdx.x & 63) * HDIM + lane * 8;
    red4(dst, r0, r1, r2, r3);
    red4(dst + 4, r4, r5, r6, r7);
    if (lane == 0) atomicAdd(&g_gcnt, cloc);
}

// ---------------- final ----------------
__global__ void k_final(const float* __restrict__ fc_W, const float* __restrict__ fc_b,
                        float* __restrict__ out) {
    __shared__ float sg[HDIM];
    int t = threadIdx.x;
    float s = 0.0f;
#pragma unroll 8
    for (int p = 0; p < 64; p++) s += g_gemb_part[p * HDIM + t];
    sg[t] = s / fmaxf((float)g_gcnt, 1.0f);
    __syncthreads();
    float acc = fc_b[t];
    const float* wr = fc_W + (size_t)t * HDIM;
#pragma unroll 8
    for (int h = 0; h < HDIM; h++) acc = fmaf(sg[h], wr[h], acc);
    out[t] = acc;
}

// ---------------- host launcher ----------------
extern "C" void kernel_launch(void* const* d_in, const int* in_sizes, int n_in,
                              void* d_out, int out_size) {
    const float* x_sub      = (const float*)d_in[0];
    const int*   ei_sub     = (const int*)  d_in[1];
    const int*   batch_sub  = (const int*)  d_in[2];
    const int*   sub_index  = (const int*)  d_in[3];
    const float* x_glob     = (const float*)d_in[4];
    const int*   ei_glob    = (const int*)  d_in[5];
    const int*   batch_glob = (const int*)  d_in[6];
    const float* W_sub      = (const float*)d_in[7];
    const float* b_sub      = (const float*)d_in[8];
    const float* W_glob     = (const float*)d_in[9];
    const float* b_glob     = (const float*)d_in[10];
    const float* fc_W       = (const float*)d_in[11];
    const float* fc_b       = (const float*)d_in[12];
    float* out = (float*)d_out;

    const int E_sub  = in_sizes[1] / 2;
    const int E_glob = in_sizes[5] / 2;

    static bool init = false;
    static float *p_dis_sub, *p_dis_glob, *p_pooled, *p_cnt;
    static __nv_bfloat16 *pb_wt_sub, *pb_wt_glob, *p_hs_sub, *p_hs_glob;
    static cudaStream_t s2, s3;
    static cudaEvent_t eStart, eD, ePad, ePW, eG;
    if (!init) {
        init = true;
        cudaGetSymbolAddress((void**)&p_dis_sub,  g_dis_sub);
        cudaGetSymbolAddress((void**)&p_dis_glob, g_dis_glob);
        cudaGetSymbolAddress((void**)&p_pooled,   g_pooled);
        cudaGetSymbolAddress((void**)&p_cnt,      g_cnt);
        cudaGetSymbolAddress((void**)&pb_wt_sub,  g_bWt_sub);
        cudaGetSymbolAddress((void**)&pb_wt_glob, g_bWt_glob);
        cudaGetSymbolAddress((void**)&p_hs_sub,   g_hs_sub);
        cudaGetSymbolAddress((void**)&p_hs_glob,  g_hs_glob);
        cudaFuncSetAttribute(k_gemm_mma, cudaFuncAttributeMaxDynamicSharedMemorySize, GEMM_SMEM);
        cudaStreamCreateWithFlags(&s2, cudaStreamNonBlocking);
        cudaStreamCreateWithFlags(&s3, cudaStreamNonBlocking);
        cudaEventCreateWithFlags(&eStart, cudaEventDisableTiming);
        cudaEventCreateWithFlags(&eD,     cudaEventDisableTiming);
        cudaEventCreateWithFlags(&ePad,   cudaEventDisableTiming);
        cudaEventCreateWithFlags(&ePW,    cudaEventDisableTiming);
        cudaEventCreateWithFlags(&eG,     cudaEventDisableTiming);
    }

    const int total_hist = E_glob + E_sub + NSUB;

    // ---- fork ----
    cudaEventRecord(eStart, 0);
    cudaStreamWaitEvent(s2, eStart, 0);
    cudaStreamWaitEvent(s3, eStart, 0);

    // ---- s2: init + combined CSR build (R12) ----
    k_init<<<1024, 256, 0, s2>>>();
    k_hist_all<<<(total_hist + 255) / 256, 256, 0, s2>>>(ei_glob, E_glob, ei_sub, E_sub,
                                                         batch_sub);
    k_scan1_all<<<384, 256, 0, s2>>>();
    cudaEventRecord(eD, s2);
    k_scan2_all<<<2, 256, 0, s2>>>();
    k_scan3_all<<<384, 256, 0, s2>>>();
    k_fill_all<<<(E_glob + E_sub + 255) / 256, 256, 0, s2>>>(ei_glob, E_glob, ei_sub, E_sub);
    k_pad_all<<<384, 256, 0, s2>>>();
    cudaEventRecord(ePad, s2);

    // ---- s3: dual W pack + glob GEMM ----
    k_pack_Wt2<<<dim3(8, 8, 2), 256, 0, s3>>>(W_glob, W_sub);
    cudaEventRecord(ePW, s3);
    cudaStreamWaitEvent(s3, eD, 0);
    k_gemm_mma<<<dim3(NGLOB / 128, 2), 256, GEMM_SMEM, s3>>>(
        x_glob, pb_wt_glob, p_hs_glob, p_dis_glob, nullptr, nullptr);
    cudaEventRecord(eG, s3);

    // ---- s0: sub GEMM/gather + fused pooled GEMM (mean + inject) + tail ----
    cudaStreamWaitEvent(0, eD, 0);
    cudaStreamWaitEvent(0, ePW, 0);
    k_gemm_mma<<<dim3(NSUB / 128, 2), 256, GEMM_SMEM>>>(
        x_sub, pb_wt_sub, p_hs_sub, p_dis_sub, nullptr, nullptr);
    cudaStreamWaitEvent(0, ePad, 0);
    k_gather_sub<<<NSUB / 32, 256>>>(batch_sub, b_sub);
    cudaStreamWaitEvent(0, eG, 0);   // glob GEMM must finish before inject-RMW epilogue
    k_gemm_mma<<<dim3(SSEG / 128, 2), 256, GEMM_SMEM>>>(
        p_pooled, pb_wt_glob, p_hs_glob, p_dis_glob, p_cnt, sub_index);
    k_gather_glob<<<NGLOB / 32, 256>>>(batch_glob, b_glob);
    k_final<<<1, 256>>>(fc_W, fc_b, out);
}

// round 15
// speedup vs baseline: 1.0188x; 1.0188x over previous
#include <cuda_runtime.h>
#include <cuda_bf16.h>
#include <cstdint>

#define HDIM   256
#define NSUB   32768
#define NGLOB  65536
#define SSEG   1024
#define ESUB_MAX   262144
#define EGLOB_MAX  1048576
#define CAPS (ESUB_MAX  + 4 * NSUB)
#define CAPG (EGLOB_MAX + 4 * NGLOB)

// ---------------- scratch ----------------
__device__ float g_dis_sub[NSUB];
__device__ float g_dis_glob[NGLOB];
__device__ float g_pooled[SSEG * HDIM];
__device__ float g_cnt[SSEG];
__device__ float g_p2[SSEG * HDIM];
__device__ float g_gemb_part[64 * HDIM];
__device__ int   g_gcnt;

__device__ int g_cntdeg_sub[NSUB];
__device__ int g_cntdeg_glob[NGLOB];
__device__ int g_off_sub[NSUB + 1];
__device__ int g_off_glob[NGLOB + 1];
__device__ int g_cur_sub[NSUB];
__device__ int g_cur_glob[NGLOB];
__device__ int g_bsum_sub[NSUB / 256];
__device__ int g_bsum_glob[NGLOB / 256];
__device__ __align__(16) int g_csr_sub[CAPS];
__device__ __align__(16) int g_csr_glob[CAPG];

__device__ __align__(16) __nv_bfloat16 g_hs_sub [(NSUB  + 1) * HDIM];
__device__ __align__(16) __nv_bfloat16 g_hs_glob[(NGLOB + 1) * HDIM];
__device__ __align__(16) __nv_bfloat16 g_bWt_sub [HDIM * HDIM];
__device__ __align__(16) __nv_bfloat16 g_bWt_glob[HDIM * HDIM];

// ---------------- PTX helpers ----------------
__device__ __forceinline__ void red4(float* p, float x, float y, float z, float w) {
    asm volatile("red.global.add.v4.f32 [%0], {%1, %2, %3, %4};"
                 :: "l"(p), "f"(x), "f"(y), "f"(z), "f"(w) : "memory");
}
__device__ __forceinline__ void cp_async16(uint32_t dst, const void* src) {
    asm volatile("cp.async.cg.shared.global [%0], [%1], 16;" :: "r"(dst), "l"(src) : "memory");
}
__device__ __forceinline__ void cp_commit() {
    asm volatile("cp.async.commit_group;" ::: "memory");
}
template <int N>
__device__ __forceinline__ void cp_wait() {
    asm volatile("cp.async.wait_group %0;" :: "n"(N) : "memory");
}
__device__ __forceinline__ void ldsm_x4(uint32_t& r0, uint32_t& r1, uint32_t& r2, uint32_t& r3,
                                        uint32_t addr) {
    asm volatile("ldmatrix.sync.aligned.m8n8.x4.shared.b16 {%0,%1,%2,%3}, [%4];"
                 : "=r"(r0), "=r"(r1), "=r"(r2), "=r"(r3) : "r"(addr));
}
__device__ __forceinline__ void mma_bf16(float* c, const uint32_t* a, const uint32_t* b) {
    asm volatile(
        "mma.sync.aligned.m16n8k16.row.col.f32.bf16.bf16.f32 "
        "{%0,%1,%2,%3}, {%4,%5,%6,%7}, {%8,%9}, {%0,%1,%2,%3};"
        : "+f"(c[0]), "+f"(c[1]), "+f"(c[2]), "+f"(c[3])
        : "r"(a[0]), "r"(a[1]), "r"(a[2]), "r"(a[3]), "r"(b[0]), "r"(b[1]));
}
__device__ __forceinline__ __nv_bfloat162 badd2(__nv_bfloat162 a, __nv_bfloat162 b) {
    return __hadd2(a, b);
}

// ---------------- combined init ----------------
__global__ void k_init() {
    int i = blockIdx.x * blockDim.x + threadIdx.x;   // grid covers 262144
    if (i < NGLOB) g_cntdeg_glob[i] = 0;
    if (i < NSUB)  g_cntdeg_sub[i]  = 0;
    if (i < SSEG * HDIM) g_pooled[i] = 0.0f;
    if (i < 64 * HDIM)   g_gemb_part[i] = 0.0f;
    if (i < SSEG)        g_cnt[i] = 0.0f;
    if (i < HDIM) {
        g_hs_sub [NSUB  * HDIM + i] = __float2bfloat16(0.0f);
        g_hs_glob[NGLOB * HDIM + i] = __float2bfloat16(0.0f);
    }
    if (i == 0) g_gcnt = 0;
}

// combined hist: glob edges, sub edges, sub batch counts
__global__ void k_hist_all(const int* __restrict__ ei_glob, int Eg,
                           const int* __restrict__ ei_sub, int Es,
                           const int* __restrict__ batch_sub) {
    int i = blockIdx.x * blockDim.x + threadIdx.x;
    if (i < Eg) {
        atomicAdd(&g_cntdeg_glob[ei_glob[Eg + i]], 1);
    } else if (i < Eg + Es) {
        int j = i - Eg;
        atomicAdd(&g_cntdeg_sub[ei_sub[Es + j]], 1);
    } else if (i < Eg + Es + NSUB) {
        int j = i - Eg - Es;
        atomicAdd(&g_cnt[batch_sub[j]], 1.0f);
    }
}

// ---- scan chain (R12) ----
__global__ void k_scan1_all() {
    __shared__ int sh[8];
    int b = blockIdx.x;
    const int* cnt;
    float* dis;
    int* bsum;
    int bb;
    if (b < 256) { cnt = g_cntdeg_glob; dis = g_dis_glob; bsum = g_bsum_glob; bb = b; }
    else         { cnt = g_cntdeg_sub;  dis = g_dis_sub;  bsum = g_bsum_sub;  bb = b - 256; }
    int i = bb * 256 + threadIdx.x;
    int c = cnt[i];
    dis[i] = rsqrtf((float)c + 1.0f);
    int p = (c + 3) & ~3;
    for (int o = 16; o; o >>= 1) p += __shfl_down_sync(~0u, p, o);
    if ((threadIdx.x & 31) == 0) sh[threadIdx.x >> 5] = p;
    __syncthreads();
    if (threadIdx.x < 8) {
        int v = sh[threadIdx.x];
        for (int o = 4; o; o >>= 1) v += __shfl_down_sync(0xff, v, o);
        if (threadIdx.x == 0) bsum[bb] = v;
    }
}
__global__ void k_scan2_all() {
    __shared__ int sh[256];
    int* bsum = blockIdx.x == 0 ? g_bsum_glob : g_bsum_sub;
    int NB    = blockIdx.x == 0 ? (NGLOB / 256) : (NSUB / 256);
    int t = threadIdx.x;
    int v = (t < NB) ? bsum[t] : 0;
    sh[t] = v;
    __syncthreads();
    for (int d = 1; d < 256; d <<= 1) {
        int u = (t >= d) ? sh[t - d] : 0;
        __syncthreads();
        sh[t] += u;
        __syncthreads();
    }
    if (t < NB) bsum[t] = sh[t] - v;
}
__global__ void k_scan3_all() {
    __shared__ int sh[256];
    int b = blockIdx.x;
    const int* cnt;
    const int* bsum;
    int* off;
    int* cur;
    int bb, N;
    if (b < 256) { cnt = g_cntdeg_glob; bsum = g_bsum_glob; off = g_off_glob; cur = g_cur_glob; bb = b; N = NGLOB; }
    else         { cnt = g_cntdeg_sub;  bsum = g_bsum_sub;  off = g_off_sub;  cur = g_cur_sub;  bb = b - 256; N = NSUB; }
    int t = threadIdx.x;
    int i = bb * 256 + t;
    int c = cnt[i];
    int p = (c + 3) & ~3;
    sh[t] = p;
    __syncthreads();
    for (int d = 1; d < 256; d <<= 1) {
        int u = (t >= d) ? sh[t - d] : 0;
        __syncthreads();
        sh[t] += u;
        __syncthreads();
    }
    int excl = sh[t] - p + bsum[bb];
    off[i] = excl;
    cur[i] = excl;
    if (i == N - 1) off[N] = excl + p;
}
__global__ void k_fill_all(const int* __restrict__ ei_glob, int Eg,
                           const int* __restrict__ ei_sub, int Es) {
    int i = blockIdx.x * blockDim.x + threadIdx.x;
    if (i < Eg) {
        int p = atomicAdd(&g_cur_glob[ei_glob[Eg + i]], 1);
        g_csr_glob[p] = ei_glob[i];
    } else if (i < Eg + Es) {
        int j = i - Eg;
        int p = atomicAdd(&g_cur_sub[ei_sub[Es + j]], 1);
        g_csr_sub[p] = ei_sub[j];
    }
}
__global__ void k_pad_all() {
    int b = blockIdx.x;
    const int* cnt;
    const int* off;
    int* csr;
    int bb, N;
    if (b < 256) { cnt = g_cntdeg_glob; off = g_off_glob; csr = g_csr_glob; bb = b; N = NGLOB; }
    else         { cnt = g_cntdeg_sub;  off = g_off_sub;  csr = g_csr_sub;  bb = b - 256; N = NSUB; }
    int i = bb * 256 + threadIdx.x;
    int c = cnt[i], o = off[i], p = (c + 3) & ~3;
    for (int j = c; j < p; j++) csr[o + j] = N;
}

// ---------------- dual W pack ----------------
__global__ void k_pack_Wt2(const float* __restrict__ Wg, const float* __restrict__ Ws) {
    __shared__ float tile[32][33];
    const float* W = blockIdx.z == 0 ? Wg : Ws;
    __nv_bfloat16* out = blockIdx.z == 0 ? g_bWt_glob : g_bWt_sub;
    int bx = blockIdx.x * 32, by = blockIdx.y * 32;
    int tx = threadIdx.x & 31, ty = threadIdx.x >> 5;
    for (int i = 0; i < 32; i += 8)
        tile[ty + i][tx] = W[(by + ty + i) * HDIM + bx + tx];
    __syncthreads();
    for (int i = 0; i < 32; i += 8)
        out[(bx + ty + i) * HDIM + by + tx] = __float2bfloat16(tile[tx][ty + i]);
}

// ---------------- bf16 mma GEMM, fp32 A in-kernel convert ----------------
// rowdiv: optional per-row divide during convert (fused mean)
#define GEMM_SMEM (32768 + 32768 + 32768)
__global__ __launch_bounds__(256, 2) void k_gemm_mma(
    const float* __restrict__ A,
    const __nv_bfloat16* __restrict__ Wt,
    __nv_bfloat16* __restrict__ Hs,
    float* __restrict__ Cf,
    const float* __restrict__ dis,
    const float* __restrict__ rowdiv)
{
    extern __shared__ __align__(16) unsigned char smem[];
    const int tid  = threadIdx.x;
    const int lane = tid & 31, warp = tid >> 5;
    const int wm = warp & 3, wn = warp >> 2;
    const int row0 = blockIdx.x * 128, col0 = blockIdx.y * 128;
    uint32_t sbase = (uint32_t)__cvta_generic_to_shared(smem);
    const uint32_t STG = sbase;
    const uint32_t ABF = sbase + 32768;
    const uint32_t BB  = sbase + 65536;

    float acc[2][8][4];
#pragma unroll
    for (int mt = 0; mt < 2; mt++)
#pragma unroll
        for (int nt = 0; nt < 8; nt++)
#pragma unroll
            for (int i = 0; i < 4; i++) acc[mt][nt][i] = 0.0f;

    auto load_A_stage = [&](int kc) {
#pragma unroll
        for (int i = 0; i < 8; i++) {
            int id = tid + i * 256;
            int r = id >> 4, c4 = id & 15;
            cp_async16(STG + (uint32_t)id * 16,
                       A + (size_t)(row0 + r) * HDIM + kc * 64 + c4 * 4);
        }
    };
    auto load_B = [&](int s, int kc) {
#pragma unroll
        for (int i = 0; i < 4; i++) {
            int id = tid + i * 256;
            int r = id >> 3, c = id & 7;
            cp_async16(BB + s * 16384 + (uint32_t)(r * 128 + ((c ^ (r & 7)) << 4)),
                       Wt + (size_t)(col0 + r) * HDIM + kc * 64 + c * 8);
        }
    };
    auto convert_A = [&](int s) {
#pragma unroll
        for (int i = 0; i < 8; i++) {
            int id = tid + i * 256;
            int r = id >> 4, c4 = id & 15;
            float4 v;
            asm volatile("ld.shared.v4.f32 {%0,%1,%2,%3}, [%4];"
                         : "=f"(v.x), "=f"(v.y), "=f"(v.z), "=f"(v.w)
                         : "r"(STG + (uint32_t)id * 16));
            if (rowdiv) {
                float inv = 1.0f / fmaxf(rowdiv[row0 + r], 1.0f);
                v.x *= inv; v.y *= inv; v.z *= inv; v.w *= inv;
            }
            __nv_bfloat162 lo = __floats2bfloat162_rn(v.x, v.y);
            __nv_bfloat162 hi = __floats2bfloat162_rn(v.z, v.w);
            int cc = c4 >> 1, half = (c4 & 1) * 8;
            uint32_t addr = ABF + s * 16384 +
                            (uint32_t)(r * 128 + ((cc ^ (r & 7)) << 4) + half);
            asm volatile("st.shared.v2.b32 [%0], {%1,%2};"
                         :: "r"(addr),
                            "r"(*reinterpret_cast<uint32_t*>(&lo)),
                            "r"(*reinterpret_cast<uint32_t*>(&hi)));
        }
    };
    auto compute = [&](int s) {
        uint32_t sA = ABF + s * 16384;
        uint32_t sB = BB + s * 16384;
#pragma unroll
        for (int kk = 0; kk < 4; kk++) {
            uint32_t af[2][4];
#pragma unroll
            for (int mt = 0; mt < 2; mt++) {
                int r = wm * 32 + mt * 16 + (lane & 15);
                int c = kk * 2 + (lane >> 4);
                ldsm_x4(af[mt][0], af[mt][1], af[mt][2], af[mt][3],
                        sA + r * 128 + ((c ^ (r & 7)) << 4));
            }
            uint32_t bf[8][2];
#pragma unroll
            for (int p = 0; p < 4; p++) {
                int r = wn * 64 + p * 16 + ((lane >> 4) << 3) + (lane & 7);
                int c = kk * 2 + ((lane >> 3) & 1);
                ldsm_x4(bf[2 * p][0], bf[2 * p][1], bf[2 * p + 1][0], bf[2 * p + 1][1],
                        sB + r * 128 + ((c ^ (r & 7)) << 4));
            }
#pragma unroll
            for (int mt = 0; mt < 2; mt++)
#pragma unroll
                for (int nt = 0; nt < 8; nt++)
                    mma_bf16(acc[mt][nt], af[mt], bf[nt]);
        }
    };

    load_A_stage(0);
    load_B(0, 0);
    cp_commit();
    cp_wait<0>();
    __syncthreads();
    convert_A(0);
    __syncthreads();

    int s = 0;
#pragma unroll 1
    for (int kc = 0; kc < 4; kc++) {
        if (kc < 3) {
            load_A_stage(kc + 1);
            load_B(s ^ 1, kc + 1);
            cp_commit();
        }
        compute(s);
        if (kc < 3) {
            cp_wait<0>();
            __syncthreads();
            convert_A(s ^ 1);
            __syncthreads();
            s ^= 1;
        }
    }

    const int g = lane >> 2, t4 = lane & 3;
#pragma unroll
    for (int mt = 0; mt < 2; mt++) {
        int r_lo = row0 + wm * 32 + mt * 16 + g;
        int r_hi = r_lo + 8;
        if (dis) {
            float dlo = dis[r_lo], dhi = dis[r_hi];
#pragma unroll
            for (int nt = 0; nt < 8; nt++) {
                int col = col0 + wn * 64 + nt * 8 + 2 * t4;
                __nv_bfloat162 lo = __floats2bfloat162_rn(acc[mt][nt][0] * dlo,
                                                          acc[mt][nt][1] * dlo);
                __nv_bfloat162 hi = __floats2bfloat162_rn(acc[mt][nt][2] * dhi,
                                                          acc[mt][nt][3] * dhi);
                *(__nv_bfloat162*)&Hs[(size_t)r_lo * HDIM + col] = lo;
                *(__nv_bfloat162*)&Hs[(size_t)r_hi * HDIM + col] = hi;
            }
        } else {
#pragma unroll
            for (int nt = 0; nt < 8; nt++) {
                int col = col0 + wn * 64 + nt * 8 + 2 * t4;
                *(float2*)&Cf[(size_t)r_lo * HDIM + col] =
                    make_float2(acc[mt][nt][0], acc[mt][nt][1]);
                *(float2*)&Cf[(size_t)r_hi * HDIM + col] =
                    make_float2(acc[mt][nt][2], acc[mt][nt][3]);
            }
        }
    }
}

// ---------------- CSR gather + fused epilogues (pad-4, int4 indices) ----------
__global__ __launch_bounds__(256) void k_gather_sub(
    const int* __restrict__ batch, const float* __restrict__ bias)
{
    const int lane = threadIdx.x & 31, grp = threadIdx.x >> 5;
    const uint4* H = (const uint4*)g_hs_sub;
    float4 b0 = ((const float4*)bias)[lane * 2];
    float4 b1 = ((const float4*)bias)[lane * 2 + 1];
#pragma unroll 1
    for (int it = 0; it < 4; it++) {
        int n = blockIdx.x * 32 + it * 8 + grp;
        int o0 = g_off_sub[n] >> 2, o1 = g_off_sub[n + 1] >> 2;
        uint4 a = H[(size_t)n * 32 + lane];
        __nv_bfloat162 A0 = *(__nv_bfloat162*)&a.x, A1 = *(__nv_bfloat162*)&a.y,
                       A2 = *(__nv_bfloat162*)&a.z, A3 = *(__nv_bfloat162*)&a.w;
#pragma unroll 1
        for (int k = o0; k < o1; k++) {
            int4 s4 = ((const int4*)g_csr_sub)[k];
            uint4 v;
            v = H[(size_t)s4.x * 32 + lane];
            A0 = badd2(A0, *(__nv_bfloat162*)&v.x); A1 = badd2(A1, *(__nv_bfloat162*)&v.y);
            A2 = badd2(A2, *(__nv_bfloat162*)&v.z); A3 = badd2(A3, *(__nv_bfloat162*)&v.w);
            v = H[(size_t)s4.y * 32 + lane];
            A0 = badd2(A0, *(__nv_bfloat162*)&v.x); A1 = badd2(A1, *(__nv_bfloat162*)&v.y);
            A2 = badd2(A2, *(__nv_bfloat162*)&v.z); A3 = badd2(A3, *(__nv_bfloat162*)&v.w);
            v = H[(size_t)s4.z * 32 + lane];
            A0 = badd2(A0, *(__nv_bfloat162*)&v.x); A1 = badd2(A1, *(__nv_bfloat162*)&v.y);
            A2 = badd2(A2, *(__nv_bfloat162*)&v.z); A3 = badd2(A3, *(__nv_bfloat162*)&v.w);
            v = H[(size_t)s4.w * 32 + lane];
            A0 = badd2(A0, *(__nv_bfloat162*)&v.x); A1 = badd2(A1, *(__nv_bfloat162*)&v.y);
            A2 = badd2(A2, *(__nv_bfloat162*)&v.z); A3 = badd2(A3, *(__nv_bfloat162*)&v.w);
        }
        float d = g_dis_sub[n];
        float2 f0 = __bfloat1622float2(A0), f1 = __bfloat1622float2(A1);
        float2 f2 = __bfloat1622float2(A2), f3 = __bfloat1622float2(A3);
        float* dst = g_pooled + (size_t)batch[n] * HDIM + lane * 8;
        red4(dst,
             fmaxf(fmaf(f0.x, d, b0.x), 0.0f), fmaxf(fmaf(f0.y, d, b0.y), 0.0f),
             fmaxf(fmaf(f1.x, d, b0.z), 0.0f), fmaxf(fmaf(f1.y, d, b0.w), 0.0f));
        red4(dst + 4,
             fmaxf(fmaf(f2.x, d, b1.x), 0.0f), fmaxf(fmaf(f2.y, d, b1.y), 0.0f),
             fmaxf(fmaf(f3.x, d, b1.z), 0.0f), fmaxf(fmaf(f3.y, d, b1.w), 0.0f));
    }
}

__global__ __launch_bounds__(256) void k_gather_glob(
    const int* __restrict__ batch, const float* __restrict__ bias)
{
    const int lane = threadIdx.x & 31, grp = threadIdx.x >> 5;
    const uint4* H = (const uint4*)g_hs_glob;
    float4 b0 = ((const float4*)bias)[lane * 2];
    float4 b1 = ((const float4*)bias)[lane * 2 + 1];
    float r0 = 0, r1 = 0, r2 = 0, r3 = 0, r4 = 0, r5 = 0, r6 = 0, r7 = 0;
    int cloc = 0;
#pragma unroll 1
    for (int it = 0; it < 4; it++) {
        int n = blockIdx.x * 32 + it * 8 + grp;
        int o0 = g_off_glob[n] >> 2, o1 = g_off_glob[n + 1] >> 2;
        uint4 a = H[(size_t)n * 32 + lane];
        __nv_bfloat162 A0 = *(__nv_bfloat162*)&a.x, A1 = *(__nv_bfloat162*)&a.y,
                       A2 = *(__nv_bfloat162*)&a.z, A3 = *(__nv_bfloat162*)&a.w;
#pragma unroll 1
        for (int k = o0; k < o1; k++) {
            int4 s4 = ((const int4*)g_csr_glob)[k];
            uint4 v;
            v = H[(size_t)s4.x * 32 + lane];
            A0 = badd2(A0, *(__nv_bfloat162*)&v.x); A1 = badd2(A1, *(__nv_bfloat162*)&v.y);
            A2 = badd2(A2, *(__nv_bfloat162*)&v.z); A3 = badd2(A3, *(__nv_bfloat162*)&v.w);
            v = H[(size_t)s4.y * 32 + lane];
            A0 = badd2(A0, *(__nv_bfloat162*)&v.x); A1 = badd2(A1, *(__nv_bfloat162*)&v.y);
            A2 = badd2(A2, *(__nv_bfloat162*)&v.z); A3 = badd2(A3, *(__nv_bfloat162*)&v.w);
            v = H[(size_t)s4.z * 32 + lane];
            A0 = badd2(A0, *(__nv_bfloat162*)&v.x); A1 = badd2(A1, *(__nv_bfloat162*)&v.y);
            A2 = badd2(A2, *(__nv_bfloat162*)&v.z); A3 = badd2(A3, *(__nv_bfloat162*)&v.w);
            v = H[(size_t)s4.w * 32 + lane];
            A0 = badd2(A0, *(__nv_bfloat162*)&v.x); A1 = badd2(A1, *(__nv_bfloat162*)&v.y);
            A2 = badd2(A2, *(__nv_bfloat162*)&v.z); A3 = badd2(A3, *(__nv_bfloat162*)&v.w);
        }
        if (batch[n] == 0) {
            float d = g_dis_glob[n];
            float2 f0 = __bfloat1622float2(A0), f1 = __bfloat1622float2(A1);
            float2 f2 = __bfloat1622float2(A2), f3 = __bfloat1622float2(A3);
            r0 += fmaxf(fmaf(f0.x, d, b0.x), 0.0f);
            r1 += fmaxf(fmaf(f0.y, d, b0.y), 0.0f);
            r2 += fmaxf(fmaf(f1.x, d, b0.z), 0.0f);
            r3 += fmaxf(fmaf(f1.y, d, b0.w), 0.0f);
            r4 += fmaxf(fmaf(f2.x, d, b1.x), 0.0f);
            r5 += fmaxf(fmaf(f2.y, d, b1.y), 0.0f);
            r6 += fmaxf(fmaf(f3.x, d, b1.z), 0.0f);
            r7 += fmaxf(fmaf(f3.y, d, b1.w), 0.0f);
            cloc++;
        }
    }
    float* dst = g_gemb_part + (size_t)(blockIdx.x & 63) * HDIM + lane * 8;
    red4(dst, r0, r1, r2, r3);
    red4(dst + 4, r4, r5, r6, r7);
    if (lane == 0) atomicAdd(&g_gcnt, cloc);
}

// ---------------- misc ----------------
__global__ void k_inject(const int* __restrict__ sub_index) {
    int idx = blockIdx.x * blockDim.x + threadIdx.x;
    if (idx >= SSEG * 128) return;
    int s = idx >> 7, c2 = idx & 127;
    int node = sub_index[s];
    float d = g_dis_glob[node];
    __nv_bfloat162* hp = (__nv_bfloat162*)g_hs_glob + (size_t)node * 128 + c2;
    float2 h = __bfloat1622float2(*hp);
    const float* p = g_p2 + (size_t)s * HDIM + c2 * 2;
    *hp = __floats2bfloat162_rn(fmaf(p[0], d, h.x), fmaf(p[1], d, h.y));
}
__global__ void k_final(const float* __restrict__ fc_W, const float* __restrict__ fc_b,
                        float* __restrict__ out) {
    __shared__ float sg[HDIM];
    int t = threadIdx.x;
    float s = 0.0f;
#pragma unroll 8
    for (int p = 0; p < 64; p++) s += g_gemb_part[p * HDIM + t];
    sg[t] = s / fmaxf((float)g_gcnt, 1.0f);
    __syncthreads();
    float acc = fc_b[t];
    const float* wr = fc_W + (size_t)t * HDIM;
#pragma unroll 8
    for (int h = 0; h < HDIM; h++) acc = fmaf(sg[h], wr[h], acc);
    out[t] = acc;
}

// ---------------- host launcher ----------------
extern "C" void kernel_launch(void* const* d_in, const int* in_sizes, int n_in,
                              void* d_out, int out_size) {
    const float* x_sub      = (const float*)d_in[0];
    const int*   ei_sub     = (const int*)  d_in[1];
    const int*   batch_sub  = (const int*)  d_in[2];
    const int*   sub_index  = (const int*)  d_in[3];
    const float* x_glob     = (const float*)d_in[4];
    const int*   ei_glob    = (const int*)  d_in[5];
    const int*   batch_glob = (const int*)  d_in[6];
    const float* W_sub      = (const float*)d_in[7];
    const float* b_sub      = (const float*)d_in[8];
    const float* W_glob     = (const float*)d_in[9];
    const float* b_glob     = (const float*)d_in[10];
    const float* fc_W       = (const float*)d_in[11];
    const float* fc_b       = (const float*)d_in[12];
    float* out = (float*)d_out;

    const int E_sub  = in_sizes[1] / 2;
    const int E_glob = in_sizes[5] / 2;

    static bool init = false;
    static float *p_dis_sub, *p_dis_glob, *p_pooled, *p_p2, *p_cnt;
    static __nv_bfloat16 *pb_wt_sub, *pb_wt_glob, *p_hs_sub, *p_hs_glob;
    static cudaStream_t s2, s3;
    static cudaEvent_t eStart, eD, ePad, ePW, eG;
    if (!init) {
        init = true;
        cudaGetSymbolAddress((void**)&p_dis_sub,  g_dis_sub);
        cudaGetSymbolAddress((void**)&p_dis_glob, g_dis_glob);
        cudaGetSymbolAddress((void**)&p_pooled,   g_pooled);
        cudaGetSymbolAddress((void**)&p_p2,       g_p2);
        cudaGetSymbolAddress((void**)&p_cnt,      g_cnt);
        cudaGetSymbolAddress((void**)&pb_wt_sub,  g_bWt_sub);
        cudaGetSymbolAddress((void**)&pb_wt_glob, g_bWt_glob);
        cudaGetSymbolAddress((void**)&p_hs_sub,   g_hs_sub);
        cudaGetSymbolAddress((void**)&p_hs_glob,  g_hs_glob);
        cudaFuncSetAttribute(k_gemm_mma, cudaFuncAttributeMaxDynamicSharedMemorySize, GEMM_SMEM);
        cudaStreamCreateWithFlags(&s2, cudaStreamNonBlocking);
        cudaStreamCreateWithFlags(&s3, cudaStreamNonBlocking);
        cudaEventCreateWithFlags(&eStart, cudaEventDisableTiming);
        cudaEventCreateWithFlags(&eD,     cudaEventDisableTiming);
        cudaEventCreateWithFlags(&ePad,   cudaEventDisableTiming);
        cudaEventCreateWithFlags(&ePW,    cudaEventDisableTiming);
        cudaEventCreateWithFlags(&eG,     cudaEventDisableTiming);
    }

    const int total_hist = E_glob + E_sub + NSUB;

    // ---- fork ----
    cudaEventRecord(eStart, 0);
    cudaStreamWaitEvent(s2, eStart, 0);
    cudaStreamWaitEvent(s3, eStart, 0);

    // ---- s2: init + combined CSR build (R12) ----
    k_init<<<1024, 256, 0, s2>>>();
    k_hist_all<<<(total_hist + 255) / 256, 256, 0, s2>>>(ei_glob, E_glob, ei_sub, E_sub,
                                                         batch_sub);
    k_scan1_all<<<384, 256, 0, s2>>>();
    cudaEventRecord(eD, s2);
    k_scan2_all<<<2, 256, 0, s2>>>();
    k_scan3_all<<<384, 256, 0, s2>>>();
    k_fill_all<<<(E_glob + E_sub + 255) / 256, 256, 0, s2>>>(ei_glob, E_glob, ei_sub, E_sub);
    k_pad_all<<<384, 256, 0, s2>>>();
    cudaEventRecord(ePad, s2);

    // ---- s3: dual W pack + glob GEMM ----
    k_pack_Wt2<<<dim3(8, 8, 2), 256, 0, s3>>>(W_glob, W_sub);
    cudaEventRecord(ePW, s3);
    cudaStreamWaitEvent(s3, eD, 0);
    k_gemm_mma<<<dim3(NGLOB / 128, 2), 256, GEMM_SMEM, s3>>>(
        x_glob, pb_wt_glob, p_hs_glob, nullptr, p_dis_glob, nullptr);
    cudaEventRecord(eG, s3);

    // ---- s0: sub GEMM/gather + pooled GEMM (fused mean, overlaps glob GEMM) ----
    cudaStreamWaitEvent(0, eD, 0);
    cudaStreamWaitEvent(0, ePW, 0);
    k_gemm_mma<<<dim3(NSUB / 128, 2), 256, GEMM_SMEM>>>(
        x_sub, pb_wt_sub, p_hs_sub, nullptr, p_dis_sub, nullptr);
    cudaStreamWaitEvent(0, ePad, 0);
    k_gather_sub<<<NSUB / 32, 256>>>(batch_sub, b_sub);
    k_gemm_mma<<<dim3(SSEG / 128, 2), 256, GEMM_SMEM>>>(
        p_pooled, pb_wt_glob, nullptr, p_p2, nullptr, p_cnt);

    // ---- join tail ----
    cudaStreamWaitEvent(0, eG, 0);
    k_inject<<<(SSEG * 128 + 255) / 256, 256>>>(sub_index);
    k_gather_glob<<<NGLOB / 32, 256>>>(batch_glob, b_glob);
    k_final<<<1, 256>>>(fc_W, fc_b, out);
}

// round 16
// speedup vs baseline: 1.0396x; 1.0204x over previous
#include <cuda_runtime.h>
#include <cuda_bf16.h>
#include <cstdint>

#define HDIM   256
#define NSUB   32768
#define NGLOB  65536
#define SSEG   1024
#define ESUB_MAX   262144
#define EGLOB_MAX  1048576
#define CAPS (ESUB_MAX  + 4 * NSUB)
#define CAPG (EGLOB_MAX + 4 * NGLOB)

// ---------------- scratch ----------------
__device__ float g_dis_sub[NSUB];
__device__ float g_dis_glob[NGLOB];
__device__ float g_pooled[SSEG * HDIM];
__device__ float g_cnt[SSEG];
__device__ float g_p2[SSEG * HDIM];
__device__ float g_gemb_part[64 * HDIM];
__device__ int   g_gcnt;

__device__ int g_cntdeg_sub[NSUB];
__device__ int g_cntdeg_glob[NGLOB];
__device__ int g_off_sub[NSUB + 1];
__device__ int g_off_glob[NGLOB + 1];
__device__ int g_cur_sub[NSUB];
__device__ int g_cur_glob[NGLOB];
__device__ int g_bsum_sub[NSUB / 256];
__device__ int g_bsum_glob[NGLOB / 256];
__device__ __align__(16) int g_csr_sub[CAPS];
__device__ __align__(16) int g_csr_glob[CAPG];

__device__ __align__(16) __nv_bfloat16 g_hs_sub [(NSUB  + 1) * HDIM];
__device__ __align__(16) __nv_bfloat16 g_hs_glob[(NGLOB + 1) * HDIM];
__device__ __align__(16) __nv_bfloat16 g_bWt_sub [HDIM * HDIM];
__device__ __align__(16) __nv_bfloat16 g_bWt_glob[HDIM * HDIM];

// ---------------- PTX helpers ----------------
__device__ __forceinline__ void red4(float* p, float x, float y, float z, float w) {
    asm volatile("red.global.add.v4.f32 [%0], {%1, %2, %3, %4};"
                 :: "l"(p), "f"(x), "f"(y), "f"(z), "f"(w) : "memory");
}
__device__ __forceinline__ void cp_async16(uint32_t dst, const void* src) {
    asm volatile("cp.async.cg.shared.global [%0], [%1], 16;" :: "r"(dst), "l"(src) : "memory");
}
__device__ __forceinline__ void cp_commit() {
    asm volatile("cp.async.commit_group;" ::: "memory");
}
template <int N>
__device__ __forceinline__ void cp_wait() {
    asm volatile("cp.async.wait_group %0;" :: "n"(N) : "memory");
}
__device__ __forceinline__ void ldsm_x4(uint32_t& r0, uint32_t& r1, uint32_t& r2, uint32_t& r3,
                                        uint32_t addr) {
    asm volatile("ldmatrix.sync.aligned.m8n8.x4.shared.b16 {%0,%1,%2,%3}, [%4];"
                 : "=r"(r0), "=r"(r1), "=r"(r2), "=r"(r3) : "r"(addr));
}
__device__ __forceinline__ void mma_bf16(float* c, const uint32_t* a, const uint32_t* b) {
    asm volatile(
        "mma.sync.aligned.m16n8k16.row.col.f32.bf16.bf16.f32 "
        "{%0,%1,%2,%3}, {%4,%5,%6,%7}, {%8,%9}, {%0,%1,%2,%3};"
        : "+f"(c[0]), "+f"(c[1]), "+f"(c[2]), "+f"(c[3])
        : "r"(a[0]), "r"(a[1]), "r"(a[2]), "r"(a[3]), "r"(b[0]), "r"(b[1]));
}
__device__ __forceinline__ __nv_bfloat162 badd2(__nv_bfloat162 a, __nv_bfloat162 b) {
    return __hadd2(a, b);
}

// ---------------- combined init ----------------
__global__ void k_init() {
    int i = blockIdx.x * blockDim.x + threadIdx.x;   // grid covers 262144
    if (i < NGLOB) g_cntdeg_glob[i] = 0;
    if (i < NSUB)  g_cntdeg_sub[i]  = 0;
    if (i < SSEG * HDIM) g_pooled[i] = 0.0f;
    if (i < 64 * HDIM)   g_gemb_part[i] = 0.0f;
    if (i < SSEG)        g_cnt[i] = 0.0f;
    if (i < HDIM) {
        g_hs_sub [NSUB  * HDIM + i] = __float2bfloat16(0.0f);
        g_hs_glob[NGLOB * HDIM + i] = __float2bfloat16(0.0f);
    }
    if (i == 0) g_gcnt = 0;
}

// combined hist: glob edges, sub edges, and sub batch counts
__global__ void k_hist_all(const int* __restrict__ ei_glob, int Eg,
                           const int* __restrict__ ei_sub, int Es,
                           const int* __restrict__ batch_sub) {
    int i = blockIdx.x * blockDim.x + threadIdx.x;
    if (i < Eg) {
        atomicAdd(&g_cntdeg_glob[ei_glob[Eg + i]], 1);
    } else if (i < Eg + Es) {
        int j = i - Eg;
        atomicAdd(&g_cntdeg_sub[ei_sub[Es + j]], 1);
    } else if (i < Eg + Es + NSUB) {
        int j = i - Eg - Es;
        atomicAdd(&g_cnt[batch_sub[j]], 1.0f);
    }
}

// ---- combined parallel padded-degree scan (pad to 4) ----
// blocks [0,256): glob, [256,384): sub
__global__ void k_scan1_all() {
    __shared__ int sh[8];
    int b = blockIdx.x;
    const int* cnt;
    float* dis;
    int* bsum;
    int bb;
    if (b < 256) { cnt = g_cntdeg_glob; dis = g_dis_glob; bsum = g_bsum_glob; bb = b; }
    else         { cnt = g_cntdeg_sub;  dis = g_dis_sub;  bsum = g_bsum_sub;  bb = b - 256; }
    int i = bb * 256 + threadIdx.x;
    int c = cnt[i];
    dis[i] = rsqrtf((float)c + 1.0f);
    int p = (c + 3) & ~3;
    for (int o = 16; o; o >>= 1) p += __shfl_down_sync(~0u, p, o);
    if ((threadIdx.x & 31) == 0) sh[threadIdx.x >> 5] = p;
    __syncthreads();
    if (threadIdx.x < 8) {
        int v = sh[threadIdx.x];
        for (int o = 4; o; o >>= 1) v += __shfl_down_sync(0xff, v, o);
        if (threadIdx.x == 0) bsum[bb] = v;
    }
}
// 2 blocks: block 0 = glob (NB=256), block 1 = sub (NB=128)
__global__ void k_scan2_all() {
    __shared__ int sh[256];
    int* bsum = blockIdx.x == 0 ? g_bsum_glob : g_bsum_sub;
    int NB    = blockIdx.x == 0 ? (NGLOB / 256) : (NSUB / 256);
    int t = threadIdx.x;
    int v = (t < NB) ? bsum[t] : 0;
    sh[t] = v;
    __syncthreads();
    for (int d = 1; d < 256; d <<= 1) {
        int u = (t >= d) ? sh[t - d] : 0;
        __syncthreads();
        sh[t] += u;
        __syncthreads();
    }
    if (t < NB) bsum[t] = sh[t] - v;
}
__global__ void k_scan3_all() {
    __shared__ int sh[256];
    int b = blockIdx.x;
    const int* cnt;
    const int* bsum;
    int* off;
    int* cur;
    int bb, N;
    if (b < 256) { cnt = g_cntdeg_glob; bsum = g_bsum_glob; off = g_off_glob; cur = g_cur_glob; bb = b; N = NGLOB; }
    else         { cnt = g_cntdeg_sub;  bsum = g_bsum_sub;  off = g_off_sub;  cur = g_cur_sub;  bb = b - 256; N = NSUB; }
    int t = threadIdx.x;
    int i = bb * 256 + t;
    int c = cnt[i];
    int p = (c + 3) & ~3;
    sh[t] = p;
    __syncthreads();
    for (int d = 1; d < 256; d <<= 1) {
        int u = (t >= d) ? sh[t - d] : 0;
        __syncthreads();
        sh[t] += u;
        __syncthreads();
    }
    int excl = sh[t] - p + bsum[bb];
    off[i] = excl;
    cur[i] = excl;
    if (i == N - 1) off[N] = excl + p;
}
__global__ void k_fill_all(const int* __restrict__ ei_glob, int Eg,
                           const int* __restrict__ ei_sub, int Es) {
    int i = blockIdx.x * blockDim.x + threadIdx.x;
    if (i < Eg) {
        int p = atomicAdd(&g_cur_glob[ei_glob[Eg + i]], 1);
        g_csr_glob[p] = ei_glob[i];
    } else if (i < Eg + Es) {
        int j = i - Eg;
        int p = atomicAdd(&g_cur_sub[ei_sub[Es + j]], 1);
        g_csr_sub[p] = ei_sub[j];
    }
}
__global__ void k_pad_all() {
    int b = blockIdx.x;
    const int* cnt;
    const int* off;
    int* csr;
    int bb, N;
    if (b < 256) { cnt = g_cntdeg_glob; off = g_off_glob; csr = g_csr_glob; bb = b; N = NGLOB; }
    else         { cnt = g_cntdeg_sub;  off = g_off_sub;  csr = g_csr_sub;  bb = b - 256; N = NSUB; }
    int i = bb * 256 + threadIdx.x;
    int c = cnt[i], o = off[i], p = (c + 3) & ~3;
    for (int j = c; j < p; j++) csr[o + j] = N;   // sentinel -> zero row
}

// ---------------- dual W pack (z = 0: glob, z = 1: sub) ----------------
__global__ void k_pack_Wt2(const float* __restrict__ Wg, const float* __restrict__ Ws) {
    __shared__ float tile[32][33];
    const float* W = blockIdx.z == 0 ? Wg : Ws;
    __nv_bfloat16* out = blockIdx.z == 0 ? g_bWt_glob : g_bWt_sub;
    int bx = blockIdx.x * 32, by = blockIdx.y * 32;
    int tx = threadIdx.x & 31, ty = threadIdx.x >> 5;
    for (int i = 0; i < 32; i += 8)
        tile[ty + i][tx] = W[(by + ty + i) * HDIM + bx + tx];
    __syncthreads();
    for (int i = 0; i < 32; i += 8)
        out[(bx + ty + i) * HDIM + by + tx] = __float2bfloat16(tile[tx][ty + i]);
}

// ---------------- bf16 mma GEMM, fp32 A in-kernel convert (R8) ----------------
#define GEMM_SMEM (32768 + 32768 + 32768)
__global__ __launch_bounds__(256, 2) void k_gemm_mma(
    const float* __restrict__ A,
    const __nv_bfloat16* __restrict__ Wt,
    __nv_bfloat16* __restrict__ Hs,
    float* __restrict__ Cf,
    const float* __restrict__ dis)
{
    extern __shared__ __align__(16) unsigned char smem[];
    const int tid  = threadIdx.x;
    const int lane = tid & 31, warp = tid >> 5;
    const int wm = warp & 3, wn = warp >> 2;
    const int row0 = blockIdx.x * 128, col0 = blockIdx.y * 128;
    uint32_t sbase = (uint32_t)__cvta_generic_to_shared(smem);
    const uint32_t STG = sbase;
    const uint32_t ABF = sbase + 32768;
    const uint32_t BB  = sbase + 65536;

    float acc[2][8][4];
#pragma unroll
    for (int mt = 0; mt < 2; mt++)
#pragma unroll
        for (int nt = 0; nt < 8; nt++)
#pragma unroll
            for (int i = 0; i < 4; i++) acc[mt][nt][i] = 0.0f;

    auto load_A_stage = [&](int kc) {
#pragma unroll
        for (int i = 0; i < 8; i++) {
            int id = tid + i * 256;
            int r = id >> 4, c4 = id & 15;
            cp_async16(STG + (uint32_t)id * 16,
                       A + (size_t)(row0 + r) * HDIM + kc * 64 + c4 * 4);
        }
    };
    auto load_B = [&](int s, int kc) {
#pragma unroll
        for (int i = 0; i < 4; i++) {
            int id = tid + i * 256;
            int r = id >> 3, c = id & 7;
            cp_async16(BB + s * 16384 + (uint32_t)(r * 128 + ((c ^ (r & 7)) << 4)),
                       Wt + (size_t)(col0 + r) * HDIM + kc * 64 + c * 8);
        }
    };
    auto convert_A = [&](int s) {
#pragma unroll
        for (int i = 0; i < 8; i++) {
            int id = tid + i * 256;
            int r = id >> 4, c4 = id & 15;
            float4 v;
            asm volatile("ld.shared.v4.f32 {%0,%1,%2,%3}, [%4];"
                         : "=f"(v.x), "=f"(v.y), "=f"(v.z), "=f"(v.w)
                         : "r"(STG + (uint32_t)id * 16));
            __nv_bfloat162 lo = __floats2bfloat162_rn(v.x, v.y);
            __nv_bfloat162 hi = __floats2bfloat162_rn(v.z, v.w);
            int cc = c4 >> 1, half = (c4 & 1) * 8;
            uint32_t addr = ABF + s * 16384 +
                            (uint32_t)(r * 128 + ((cc ^ (r & 7)) << 4) + half);
            asm volatile("st.shared.v2.b32 [%0], {%1,%2};"
                         :: "r"(addr),
                            "r"(*reinterpret_cast<uint32_t*>(&lo)),
                            "r"(*reinterpret_cast<uint32_t*>(&hi)));
        }
    };
    auto compute = [&](int s) {
        uint32_t sA = ABF + s * 16384;
        uint32_t sB = BB + s * 16384;
#pragma unroll
        for (int kk = 0; kk < 4; kk++) {
            uint32_t af[2][4];
#pragma unroll
            for (int mt = 0; mt < 2; mt++) {
                int r = wm * 32 + mt * 16 + (lane & 15);
                int c = kk * 2 + (lane >> 4);
                ldsm_x4(af[mt][0], af[mt][1], af[mt][2], af[mt][3],
                        sA + r * 128 + ((c ^ (r & 7)) << 4));
            }
            uint32_t bf[8][2];
#pragma unroll
            for (int p = 0; p < 4; p++) {
                int r = wn * 64 + p * 16 + ((lane >> 4) << 3) + (lane & 7);
                int c = kk * 2 + ((lane >> 3) & 1);
                ldsm_x4(bf[2 * p][0], bf[2 * p][1], bf[2 * p + 1][0], bf[2 * p + 1][1],
                        sB + r * 128 + ((c ^ (r & 7)) << 4));
            }
#pragma unroll
            for (int mt = 0; mt < 2; mt++)
#pragma unroll
                for (int nt = 0; nt < 8; nt++)
                    mma_bf16(acc[mt][nt], af[mt], bf[nt]);
        }
    };

    load_A_stage(0);
    load_B(0, 0);
    cp_commit();
    cp_wait<0>();
    __syncthreads();
    convert_A(0);
    __syncthreads();

    int s = 0;
#pragma unroll 1
    for (int kc = 0; kc < 4; kc++) {
        if (kc < 3) {
            load_A_stage(kc + 1);
            load_B(s ^ 1, kc + 1);
            cp_commit();
        }
        compute(s);
        if (kc < 3) {
            cp_wait<0>();
            __syncthreads();
            convert_A(s ^ 1);
            __syncthreads();
            s ^= 1;
        }
    }

    const int g = lane >> 2, t4 = lane & 3;
#pragma unroll
    for (int mt = 0; mt < 2; mt++) {
        int r_lo = row0 + wm * 32 + mt * 16 + g;
        int r_hi = r_lo + 8;
        if (dis) {
            float dlo = dis[r_lo], dhi = dis[r_hi];
#pragma unroll
            for (int nt = 0; nt < 8; nt++) {
                int col = col0 + wn * 64 + nt * 8 + 2 * t4;
                __nv_bfloat162 lo = __floats2bfloat162_rn(acc[mt][nt][0] * dlo,
                                                          acc[mt][nt][1] * dlo);
                __nv_bfloat162 hi = __floats2bfloat162_rn(acc[mt][nt][2] * dhi,
                                                          acc[mt][nt][3] * dhi);
                *(__nv_bfloat162*)&Hs[(size_t)r_lo * HDIM + col] = lo;
                *(__nv_bfloat162*)&Hs[(size_t)r_hi * HDIM + col] = hi;
            }
        } else {
#pragma unroll
            for (int nt = 0; nt < 8; nt++) {
                int col = col0 + wn * 64 + nt * 8 + 2 * t4;
                *(float2*)&Cf[(size_t)r_lo * HDIM + col] =
                    make_float2(acc[mt][nt][0], acc[mt][nt][1]);
                *(float2*)&Cf[(size_t)r_hi * HDIM + col] =
                    make_float2(acc[mt][nt][2], acc[mt][nt][3]);
            }
        }
    }
}

// ---------------- CSR gather + fused epilogues (R8: pad-4, int4 indices) ----------
__global__ __launch_bounds__(256) void k_gather_sub(
    const int* __restrict__ batch, const float* __restrict__ bias)
{
    const int lane = threadIdx.x & 31, grp = threadIdx.x >> 5;
    const uint4* H = (const uint4*)g_hs_sub;
    float4 b0 = ((const float4*)bias)[lane * 2];
    float4 b1 = ((const float4*)bias)[lane * 2 + 1];
#pragma unroll 1
    for (int it = 0; it < 4; it++) {
        int n = blockIdx.x * 32 + it * 8 + grp;
        int o0 = g_off_sub[n] >> 2, o1 = g_off_sub[n + 1] >> 2;
        uint4 a = H[(size_t)n * 32 + lane];
        __nv_bfloat162 A0 = *(__nv_bfloat162*)&a.x, A1 = *(__nv_bfloat162*)&a.y,
                       A2 = *(__nv_bfloat162*)&a.z, A3 = *(__nv_bfloat162*)&a.w;
#pragma unroll 1
        for (int k = o0; k < o1; k++) {
            int4 s4 = ((const int4*)g_csr_sub)[k];
            uint4 v;
            v = H[(size_t)s4.x * 32 + lane];
            A0 = badd2(A0, *(__nv_bfloat162*)&v.x); A1 = badd2(A1, *(__nv_bfloat162*)&v.y);
            A2 = badd2(A2, *(__nv_bfloat162*)&v.z); A3 = badd2(A3, *(__nv_bfloat162*)&v.w);
            v = H[(size_t)s4.y * 32 + lane];
            A0 = badd2(A0, *(__nv_bfloat162*)&v.x); A1 = badd2(A1, *(__nv_bfloat162*)&v.y);
            A2 = badd2(A2, *(__nv_bfloat162*)&v.z); A3 = badd2(A3, *(__nv_bfloat162*)&v.w);
            v = H[(size_t)s4.z * 32 + lane];
            A0 = badd2(A0, *(__nv_bfloat162*)&v.x); A1 = badd2(A1, *(__nv_bfloat162*)&v.y);
            A2 = badd2(A2, *(__nv_bfloat162*)&v.z); A3 = badd2(A3, *(__nv_bfloat162*)&v.w);
            v = H[(size_t)s4.w * 32 + lane];
            A0 = badd2(A0, *(__nv_bfloat162*)&v.x); A1 = badd2(A1, *(__nv_bfloat162*)&v.y);
            A2 = badd2(A2, *(__nv_bfloat162*)&v.z); A3 = badd2(A3, *(__nv_bfloat162*)&v.w);
        }
        float d = g_dis_sub[n];
        float2 f0 = __bfloat1622float2(A0), f1 = __bfloat1622float2(A1);
        float2 f2 = __bfloat1622float2(A2), f3 = __bfloat1622float2(A3);
        float* dst = g_pooled + (size_t)batch[n] * HDIM + lane * 8;
        red4(dst,
             fmaxf(fmaf(f0.x, d, b0.x), 0.0f), fmaxf(fmaf(f0.y, d, b0.y), 0.0f),
             fmaxf(fmaf(f1.x, d, b0.z), 0.0f), fmaxf(fmaf(f1.y, d, b0.w), 0.0f));
        red4(dst + 4,
             fmaxf(fmaf(f2.x, d, b1.x), 0.0f), fmaxf(fmaf(f2.y, d, b1.y), 0.0f),
             fmaxf(fmaf(f3.x, d, b1.z), 0.0f), fmaxf(fmaf(f3.y, d, b1.w), 0.0f));
    }
}

__global__ __launch_bounds__(256) void k_gather_glob(
    const int* __restrict__ batch, const float* __restrict__ bias)
{
    const int lane = threadIdx.x & 31, grp = threadIdx.x >> 5;
    const uint4* H = (const uint4*)g_hs_glob;
    float4 b0 = ((const float4*)bias)[lane * 2];
    float4 b1 = ((const float4*)bias)[lane * 2 + 1];
    float r0 = 0, r1 = 0, r2 = 0, r3 = 0, r4 = 0, r5 = 0, r6 = 0, r7 = 0;
    int cloc = 0;
#pragma unroll 1
    for (int it = 0; it < 4; it++) {
        int n = blockIdx.x * 32 + it * 8 + grp;
        int o0 = g_off_glob[n] >> 2, o1 = g_off_glob[n + 1] >> 2;
        uint4 a = H[(size_t)n * 32 + lane];
        __nv_bfloat162 A0 = *(__nv_bfloat162*)&a.x, A1 = *(__nv_bfloat162*)&a.y,
                       A2 = *(__nv_bfloat162*)&a.z, A3 = *(__nv_bfloat162*)&a.w;
#pragma unroll 1
        for (int k = o0; k < o1; k++) {
            int4 s4 = ((const int4*)g_csr_glob)[k];
            uint4 v;
            v = H[(size_t)s4.x * 32 + lane];
            A0 = badd2(A0, *(__nv_bfloat162*)&v.x); A1 = badd2(A1, *(__nv_bfloat162*)&v.y);
            A2 = badd2(A2, *(__nv_bfloat162*)&v.z); A3 = badd2(A3, *(__nv_bfloat162*)&v.w);
            v = H[(size_t)s4.y * 32 + lane];
            A0 = badd2(A0, *(__nv_bfloat162*)&v.x); A1 = badd2(A1, *(__nv_bfloat162*)&v.y);
            A2 = badd2(A2, *(__nv_bfloat162*)&v.z); A3 = badd2(A3, *(__nv_bfloat162*)&v.w);
            v = H[(size_t)s4.z * 32 + lane];
            A0 = badd2(A0, *(__nv_bfloat162*)&v.x); A1 = badd2(A1, *(__nv_bfloat162*)&v.y);
            A2 = badd2(A2, *(__nv_bfloat162*)&v.z); A3 = badd2(A3, *(__nv_bfloat162*)&v.w);
            v = H[(size_t)s4.w * 32 + lane];
            A0 = badd2(A0, *(__nv_bfloat162*)&v.x); A1 = badd2(A1, *(__nv_bfloat162*)&v.y);
            A2 = badd2(A2, *(__nv_bfloat162*)&v.z); A3 = badd2(A3, *(__nv_bfloat162*)&v.w);
        }
        if (batch[n] == 0) {
            float d = g_dis_glob[n];
            float2 f0 = __bfloat1622float2(A0), f1 = __bfloat1622float2(A1);
            float2 f2 = __bfloat1622float2(A2), f3 = __bfloat1622float2(A3);
            r0 += fmaxf(fmaf(f0.x, d, b0.x), 0.0f);
            r1 += fmaxf(fmaf(f0.y, d, b0.y), 0.0f);
            r2 += fmaxf(fmaf(f1.x, d, b0.z), 0.0f);
            r3 += fmaxf(fmaf(f1.y, d, b0.w), 0.0f);
            r4 += fmaxf(fmaf(f2.x, d, b1.x), 0.0f);
            r5 += fmaxf(fmaf(f2.y, d, b1.y), 0.0f);
            r6 += fmaxf(fmaf(f3.x, d, b1.z), 0.0f);
            r7 += fmaxf(fmaf(f3.y, d, b1.w), 0.0f);
            cloc++;
        }
    }
    float* dst = g_gemb_part + (size_t)(blockIdx.x & 63) * HDIM + lane * 8;
    red4(dst, r0, r1, r2, r3);
    red4(dst + 4, r4, r5, r6, r7);
    if (lane == 0) atomicAdd(&g_gcnt, cloc);
}

// ---------------- misc ----------------
__global__ void k_pool_finish() {
    int vid = blockIdx.x * blockDim.x + threadIdx.x;
    if (vid >= SSEG * 64) return;
    int s = vid >> 6;
    float inv = 1.0f / fmaxf(g_cnt[s], 1.0f);
    float4 v = ((const float4*)g_pooled)[vid];
    v.x *= inv; v.y *= inv; v.z *= inv; v.w *= inv;
    ((float4*)g_pooled)[vid] = v;
}
__global__ void k_inject(const int* __restrict__ sub_index) {
    int idx = blockIdx.x * blockDim.x + threadIdx.x;
    if (idx >= SSEG * 128) return;
    int s = idx >> 7, c2 = idx & 127;
    int node = sub_index[s];
    float d = g_dis_glob[node];
    __nv_bfloat162* hp = (__nv_bfloat162*)g_hs_glob + (size_t)node * 128 + c2;
    float2 h = __bfloat1622float2(*hp);
    const float* p = g_p2 + (size_t)s * HDIM + c2 * 2;
    *hp = __floats2bfloat162_rn(fmaf(p[0], d, h.x), fmaf(p[1], d, h.y));
}
__global__ void k_final(const float* __restrict__ fc_W, const float* __restrict__ fc_b,
                        float* __restrict__ out) {
    __shared__ float sg[HDIM];
    int t = threadIdx.x;
    float s = 0.0f;
#pragma unroll 8
    for (int p = 0; p < 64; p++) s += g_gemb_part[p * HDIM + t];
    sg[t] = s / fmaxf((float)g_gcnt, 1.0f);
    __syncthreads();
    float acc = fc_b[t];
    const float* wr = fc_W + (size_t)t * HDIM;
#pragma unroll 8
    for (int h = 0; h < HDIM; h++) acc = fmaf(sg[h], wr[h], acc);
    out[t] = acc;
}

// ---------------- host launcher ----------------
extern "C" void kernel_launch(void* const* d_in, const int* in_sizes, int n_in,
                              void* d_out, int out_size) {
    const float* x_sub      = (const float*)d_in[0];
    const int*   ei_sub     = (const int*)  d_in[1];
    const int*   batch_sub  = (const int*)  d_in[2];
    const int*   sub_index  = (const int*)  d_in[3];
    const float* x_glob     = (const float*)d_in[4];
    const int*   ei_glob    = (const int*)  d_in[5];
    const int*   batch_glob = (const int*)  d_in[6];
    const float* W_sub      = (const float*)d_in[7];
    const float* b_sub      = (const float*)d_in[8];
    const float* W_glob     = (const float*)d_in[9];
    const float* b_glob     = (const float*)d_in[10];
    const float* fc_W       = (const float*)d_in[11];
    const float* fc_b       = (const float*)d_in[12];
    float* out = (float*)d_out;

    const int E_sub  = in_sizes[1] / 2;
    const int E_glob = in_sizes[5] / 2;

    static bool init = false;
    static float *p_dis_sub, *p_dis_glob, *p_pooled, *p_p2;
    static __nv_bfloat16 *pb_wt_sub, *pb_wt_glob, *p_hs_sub, *p_hs_glob;
    static cudaStream_t s2, s3;
    static cudaEvent_t eStart, eI, eD, ePad, ePW, eG;
    if (!init) {
        init = true;
        cudaGetSymbolAddress((void**)&p_dis_sub,  g_dis_sub);
        cudaGetSymbolAddress((void**)&p_dis_glob, g_dis_glob);
        cudaGetSymbolAddress((void**)&p_pooled,   g_pooled);
        cudaGetSymbolAddress((void**)&p_p2,       g_p2);
        cudaGetSymbolAddress((void**)&pb_wt_sub,  g_bWt_sub);
        cudaGetSymbolAddress((void**)&pb_wt_glob, g_bWt_glob);
        cudaGetSymbolAddress((void**)&p_hs_sub,   g_hs_sub);
        cudaGetSymbolAddress((void**)&p_hs_glob,  g_hs_glob);
        cudaFuncSetAttribute(k_gemm_mma, cudaFuncAttributeMaxDynamicSharedMemorySize, GEMM_SMEM);
        cudaStreamCreateWithFlags(&s2, cudaStreamNonBlocking);
        cudaStreamCreateWithFlags(&s3, cudaStreamNonBlocking);
        cudaEventCreateWithFlags(&eStart, cudaEventDisableTiming);
        cudaEventCreateWithFlags(&eI,     cudaEventDisableTiming);
        cudaEventCreateWithFlags(&eD,     cudaEventDisableTiming);
        cudaEventCreateWithFlags(&ePad,   cudaEventDisableTiming);
        cudaEventCreateWithFlags(&ePW,    cudaEventDisableTiming);
        cudaEventCreateWithFlags(&eG,     cudaEventDisableTiming);
    }

    const int total_hist = E_glob + E_sub + NSUB;

    // ---- fork ----
    cudaEventRecord(eStart, 0);
    cudaStreamWaitEvent(s2, eStart, 0);
    cudaStreamWaitEvent(s3, eStart, 0);

    // ---- s2: init + combined CSR build (both graphs) ----
    k_init<<<1024, 256, 0, s2>>>();
    cudaEventRecord(eI, s2);
    k_hist_all<<<(total_hist + 255) / 256, 256, 0, s2>>>(ei_glob, E_glob, ei_sub, E_sub,
                                                         batch_sub);
    k_scan1_all<<<384, 256, 0, s2>>>();
    cudaEventRecord(eD, s2);
    k_scan2_all<<<2, 256, 0, s2>>>();
    k_scan3_all<<<384, 256, 0, s2>>>();
    k_fill_all<<<(E_glob + E_sub + 255) / 256, 256, 0, s2>>>(ei_glob, E_glob, ei_sub, E_sub);
    k_pad_all<<<384, 256, 0, s2>>>();
    cudaEventRecord(ePad, s2);

    // ---- s3: dual W pack + glob GEMM ----
    k_pack_Wt2<<<dim3(8, 8, 2), 256, 0, s3>>>(W_glob, W_sub);
    cudaEventRecord(ePW, s3);
    cudaStreamWaitEvent(s3, eD, 0);
    k_gemm_mma<<<dim3(NGLOB / 128, 2), 256, GEMM_SMEM, s3>>>(x_glob, pb_wt_glob,
                                                             p_hs_glob, nullptr, p_dis_glob);
    cudaEventRecord(eG, s3);

    // ---- s0: sub GEMM/gather + pooled GEMM + join tail ----
    cudaStreamWaitEvent(0, eD, 0);
    cudaStreamWaitEvent(0, ePW, 0);
    k_gemm_mma<<<dim3(NSUB / 128, 2), 256, GEMM_SMEM>>>(x_sub, pb_wt_sub,
                                                        p_hs_sub, nullptr, p_dis_sub);
    cudaStreamWaitEvent(0, ePad, 0);
    k_gather_sub<<<NSUB / 32, 256>>>(batch_sub, b_sub);
    k_pool_finish<<<(SSEG * 64 + 255) / 256, 256>>>();
    k_gemm_mma<<<dim3(SSEG / 128, 2), 256, GEMM_SMEM>>>(p_pooled, pb_wt_glob,
                                                        nullptr, p_p2, nullptr);

    cudaStreamWaitEvent(0, eG, 0);
    k_inject<<<(SSEG * 128 + 255) / 256, 256>>>(sub_index);
    k_gather_glob<<<NGLOB / 32, 256>>>(batch_glob, b_glob);
    k_final<<<1, 256>>>(fc_W, fc_b, out);
}

// round 17
// speedup vs baseline: 1.0606x; 1.0202x over previous
#include <cuda_runtime.h>
#include <cuda_bf16.h>
#include <cstdint>

#define HDIM   256
#define NSUB   32768
#define NGLOB  65536
#define SSEG   1024
#define ESUB_MAX   262144
#define EGLOB_MAX  1048576
#define CAPS (ESUB_MAX  + 4 * NSUB)
#define CAPG (EGLOB_MAX + 4 * NGLOB)

// ---------------- scratch ----------------
__device__ float g_dis_sub[NSUB];
__device__ float g_dis_glob[NGLOB];
__device__ float g_pooled[SSEG * HDIM];
__device__ float g_cnt[SSEG];
__device__ float g_p2[SSEG * HDIM];
__device__ float g_gemb_part[64 * HDIM];
__device__ int   g_gcnt;

__device__ int g_cntdeg_sub[NSUB];
__device__ int g_cntdeg_glob[NGLOB];
__device__ int g_off_sub[NSUB + 1];
__device__ int g_off_glob[NGLOB + 1];
__device__ int g_cur_sub[NSUB];
__device__ int g_cur_glob[NGLOB];
__device__ int g_bsum_sub[NSUB / 256];
__device__ int g_bsum_glob[NGLOB / 256];
__device__ __align__(16) int g_csr_sub[CAPS];
__device__ __align__(16) int g_csr_glob[CAPG];

__device__ __align__(16) __nv_bfloat16 g_hs_sub [(NSUB  + 1) * HDIM];
__device__ __align__(16) __nv_bfloat16 g_hs_glob[(NGLOB + 1) * HDIM];
__device__ __align__(16) __nv_bfloat16 g_bWt_sub [HDIM * HDIM];
__device__ __align__(16) __nv_bfloat16 g_bWt_glob[HDIM * HDIM];

// ---------------- PTX helpers ----------------
__device__ __forceinline__ void red4(float* p, float x, float y, float z, float w) {
    asm volatile("red.global.add.v4.f32 [%0], {%1, %2, %3, %4};"
                 :: "l"(p), "f"(x), "f"(y), "f"(z), "f"(w) : "memory");
}
__device__ __forceinline__ void cp_async16(uint32_t dst, const void* src) {
    asm volatile("cp.async.cg.shared.global [%0], [%1], 16;" :: "r"(dst), "l"(src) : "memory");
}
__device__ __forceinline__ void cp_commit() {
    asm volatile("cp.async.commit_group;" ::: "memory");
}
template <int N>
__device__ __forceinline__ void cp_wait() {
    asm volatile("cp.async.wait_group %0;" :: "n"(N) : "memory");
}
__device__ __forceinline__ void ldsm_x4(uint32_t& r0, uint32_t& r1, uint32_t& r2, uint32_t& r3,
                                        uint32_t addr) {
    asm volatile("ldmatrix.sync.aligned.m8n8.x4.shared.b16 {%0,%1,%2,%3}, [%4];"
                 : "=r"(r0), "=r"(r1), "=r"(r2), "=r"(r3) : "r"(addr));
}
__device__ __forceinline__ void mma_bf16(float* c, const uint32_t* a, const uint32_t* b) {
    asm volatile(
        "mma.sync.aligned.m16n8k16.row.col.f32.bf16.bf16.f32 "
        "{%0,%1,%2,%3}, {%4,%5,%6,%7}, {%8,%9}, {%0,%1,%2,%3};"
        : "+f"(c[0]), "+f"(c[1]), "+f"(c[2]), "+f"(c[3])
        : "r"(a[0]), "r"(a[1]), "r"(a[2]), "r"(a[3]), "r"(b[0]), "r"(b[1]));
}
__device__ __forceinline__ __nv_bfloat162 badd2(__nv_bfloat162 a, __nv_bfloat162 b) {
    return __hadd2(a, b);
}

// ---------------- combined init ----------------
__global__ void k_init() {
    int i = blockIdx.x * blockDim.x + threadIdx.x;   // grid covers 262144
    if (i < NGLOB) g_cntdeg_glob[i] = 0;
    if (i < NSUB)  g_cntdeg_sub[i]  = 0;
    if (i < 64 * HDIM) g_gemb_part[i] = 0.0f;
    if (i < SSEG)      g_cnt[i] = 0.0f;
    if (i < HDIM) {
        g_hs_sub [NSUB  * HDIM + i] = __float2bfloat16(0.0f);
        g_hs_glob[NGLOB * HDIM + i] = __float2bfloat16(0.0f);
    }
    if (i == 0) g_gcnt = 0;
}

// combined hist: glob edges, sub edges, and sub batch counts
__global__ void k_hist_all(const int* __restrict__ ei_glob, int Eg,
                           const int* __restrict__ ei_sub, int Es,
                           const int* __restrict__ batch_sub) {
    int i = blockIdx.x * blockDim.x + threadIdx.x;
    if (i < Eg) {
        atomicAdd(&g_cntdeg_glob[ei_glob[Eg + i]], 1);
    } else if (i < Eg + Es) {
        int j = i - Eg;
        atomicAdd(&g_cntdeg_sub[ei_sub[Es + j]], 1);
    } else if (i < Eg + Es + NSUB) {
        int j = i - Eg - Es;
        atomicAdd(&g_cnt[batch_sub[j]], 1.0f);
    }
}

// ---- combined parallel padded-degree scan (pad to 4) ----
__global__ void k_scan1_all() {
    __shared__ int sh[8];
    int b = blockIdx.x;
    const int* cnt;
    float* dis;
    int* bsum;
    int bb;
    if (b < 256) { cnt = g_cntdeg_glob; dis = g_dis_glob; bsum = g_bsum_glob; bb = b; }
    else         { cnt = g_cntdeg_sub;  dis = g_dis_sub;  bsum = g_bsum_sub;  bb = b - 256; }
    int i = bb * 256 + threadIdx.x;
    int c = cnt[i];
    dis[i] = rsqrtf((float)c + 1.0f);
    int p = (c + 3) & ~3;
    for (int o = 16; o; o >>= 1) p += __shfl_down_sync(~0u, p, o);
    if ((threadIdx.x & 31) == 0) sh[threadIdx.x >> 5] = p;
    __syncthreads();
    if (threadIdx.x < 8) {
        int v = sh[threadIdx.x];
        for (int o = 4; o; o >>= 1) v += __shfl_down_sync(0xff, v, o);
        if (threadIdx.x == 0) bsum[bb] = v;
    }
}
__global__ void k_scan2_all() {
    __shared__ int sh[256];
    int* bsum = blockIdx.x == 0 ? g_bsum_glob : g_bsum_sub;
    int NB    = blockIdx.x == 0 ? (NGLOB / 256) : (NSUB / 256);
    int t = threadIdx.x;
    int v = (t < NB) ? bsum[t] : 0;
    sh[t] = v;
    __syncthreads();
    for (int d = 1; d < 256; d <<= 1) {
        int u = (t >= d) ? sh[t - d] : 0;
        __syncthreads();
        sh[t] += u;
        __syncthreads();
    }
    if (t < NB) bsum[t] = sh[t] - v;
}
__global__ void k_scan3_all() {
    __shared__ int sh[256];
    int b = blockIdx.x;
    const int* cnt;
    const int* bsum;
    int* off;
    int* cur;
    int bb, N;
    if (b < 256) { cnt = g_cntdeg_glob; bsum = g_bsum_glob; off = g_off_glob; cur = g_cur_glob; bb = b; N = NGLOB; }
    else         { cnt = g_cntdeg_sub;  bsum = g_bsum_sub;  off = g_off_sub;  cur = g_cur_sub;  bb = b - 256; N = NSUB; }
    int t = threadIdx.x;
    int i = bb * 256 + t;
    int c = cnt[i];
    int p = (c + 3) & ~3;
    sh[t] = p;
    __syncthreads();
    for (int d = 1; d < 256; d <<= 1) {
        int u = (t >= d) ? sh[t - d] : 0;
        __syncthreads();
        sh[t] += u;
        __syncthreads();
    }
    int excl = sh[t] - p + bsum[bb];
    off[i] = excl;
    cur[i] = excl;
    if (i == N - 1) off[N] = excl + p;
}
__global__ void k_fill_all(const int* __restrict__ ei_glob, int Eg,
                           const int* __restrict__ ei_sub, int Es) {
    int i = blockIdx.x * blockDim.x + threadIdx.x;
    if (i < Eg) {
        int p = atomicAdd(&g_cur_glob[ei_glob[Eg + i]], 1);
        g_csr_glob[p] = ei_glob[i];
    } else if (i < Eg + Es) {
        int j = i - Eg;
        int p = atomicAdd(&g_cur_sub[ei_sub[Es + j]], 1);
        g_csr_sub[p] = ei_sub[j];
    }
}
__global__ void k_pad_all() {
    int b = blockIdx.x;
    const int* cnt;
    const int* off;
    int* csr;
    int bb, N;
    if (b < 256) { cnt = g_cntdeg_glob; off = g_off_glob; csr = g_csr_glob; bb = b; N = NGLOB; }
    else         { cnt = g_cntdeg_sub;  off = g_off_sub;  csr = g_csr_sub;  bb = b - 256; N = NSUB; }
    int i = bb * 256 + threadIdx.x;
    int c = cnt[i], o = off[i], p = (c + 3) & ~3;
    for (int j = c; j < p; j++) csr[o + j] = N;   // sentinel -> zero row
}

// ---------------- dual W pack ----------------
__global__ void k_pack_Wt2(const float* __restrict__ Wg, const float* __restrict__ Ws) {
    __shared__ float tile[32][33];
    const float* W = blockIdx.z == 0 ? Wg : Ws;
    __nv_bfloat16* out = blockIdx.z == 0 ? g_bWt_glob : g_bWt_sub;
    int bx = blockIdx.x * 32, by = blockIdx.y * 32;
    int tx = threadIdx.x & 31, ty = threadIdx.x >> 5;
    for (int i = 0; i < 32; i += 8)
        tile[ty + i][tx] = W[(by + ty + i) * HDIM + bx + tx];
    __syncthreads();
    for (int i = 0; i < 32; i += 8)
        out[(bx + ty + i) * HDIM + by + tx] = __float2bfloat16(tile[tx][ty + i]);
}

// ---------------- bf16 mma GEMM, fp32 A in-kernel convert ----------------
#define GEMM_SMEM (32768 + 32768 + 32768)
__global__ __launch_bounds__(256, 2) void k_gemm_mma(
    const float* __restrict__ A,
    const __nv_bfloat16* __restrict__ Wt,
    __nv_bfloat16* __restrict__ Hs,
    float* __restrict__ Cf,
    const float* __restrict__ dis)
{
    extern __shared__ __align__(16) unsigned char smem[];
    const int tid  = threadIdx.x;
    const int lane = tid & 31, warp = tid >> 5;
    const int wm = warp & 3, wn = warp >> 2;
    const int row0 = blockIdx.x * 128, col0 = blockIdx.y * 128;
    uint32_t sbase = (uint32_t)__cvta_generic_to_shared(smem);
    const uint32_t STG = sbase;
    const uint32_t ABF = sbase + 32768;
    const uint32_t BB  = sbase + 65536;

    float acc[2][8][4];
#pragma unroll
    for (int mt = 0; mt < 2; mt++)
#pragma unroll
        for (int nt = 0; nt < 8; nt++)
#pragma unroll
            for (int i = 0; i < 4; i++) acc[mt][nt][i] = 0.0f;

    auto load_A_stage = [&](int kc) {
#pragma unroll
        for (int i = 0; i < 8; i++) {
            int id = tid + i * 256;
            int r = id >> 4, c4 = id & 15;
            cp_async16(STG + (uint32_t)id * 16,
                       A + (size_t)(row0 + r) * HDIM + kc * 64 + c4 * 4);
        }
    };
    auto load_B = [&](int s, int kc) {
#pragma unroll
        for (int i = 0; i < 4; i++) {
            int id = tid + i * 256;
            int r = id >> 3, c = id & 7;
            cp_async16(BB + s * 16384 + (uint32_t)(r * 128 + ((c ^ (r & 7)) << 4)),
                       Wt + (size_t)(col0 + r) * HDIM + kc * 64 + c * 8);
        }
    };
    auto convert_A = [&](int s) {
#pragma unroll
        for (int i = 0; i < 8; i++) {
            int id = tid + i * 256;
            int r = id >> 4, c4 = id & 15;
            float4 v;
            asm volatile("ld.shared.v4.f32 {%0,%1,%2,%3}, [%4];"
                         : "=f"(v.x), "=f"(v.y), "=f"(v.z), "=f"(v.w)
                         : "r"(STG + (uint32_t)id * 16));
            __nv_bfloat162 lo = __floats2bfloat162_rn(v.x, v.y);
            __nv_bfloat162 hi = __floats2bfloat162_rn(v.z, v.w);
            int cc = c4 >> 1, half = (c4 & 1) * 8;
            uint32_t addr = ABF + s * 16384 +
                            (uint32_t)(r * 128 + ((cc ^ (r & 7)) << 4) + half);
            asm volatile("st.shared.v2.b32 [%0], {%1,%2};"
                         :: "r"(addr),
                            "r"(*reinterpret_cast<uint32_t*>(&lo)),
                            "r"(*reinterpret_cast<uint32_t*>(&hi)));
        }
    };
    auto compute = [&](int s) {
        uint32_t sA = ABF + s * 16384;
        uint32_t sB = BB + s * 16384;
#pragma unroll
        for (int kk = 0; kk < 4; kk++) {
            uint32_t af[2][4];
#pragma unroll
            for (int mt = 0; mt < 2; mt++) {
                int r = wm * 32 + mt * 16 + (lane & 15);
                int c = kk * 2 + (lane >> 4);
                ldsm_x4(af[mt][0], af[mt][1], af[mt][2], af[mt][3],
                        sA + r * 128 + ((c ^ (r & 7)) << 4));
            }
            uint32_t bf[8][2];
#pragma unroll
            for (int p = 0; p < 4; p++) {
                int r = wn * 64 + p * 16 + ((lane >> 4) << 3) + (lane & 7);
                int c = kk * 2 + ((lane >> 3) & 1);
                ldsm_x4(bf[2 * p][0], bf[2 * p][1], bf[2 * p + 1][0], bf[2 * p + 1][1],
                        sB + r * 128 + ((c ^ (r & 7)) << 4));
            }
#pragma unroll
            for (int mt = 0; mt < 2; mt++)
#pragma unroll
                for (int nt = 0; nt < 8; nt++)
                    mma_bf16(acc[mt][nt], af[mt], bf[nt]);
        }
    };

    load_A_stage(0);
    load_B(0, 0);
    cp_commit();
    cp_wait<0>();
    __syncthreads();
    convert_A(0);
    __syncthreads();

    int s = 0;
#pragma unroll 1
    for (int kc = 0; kc < 4; kc++) {
        if (kc < 3) {
            load_A_stage(kc + 1);
            load_B(s ^ 1, kc + 1);
            cp_commit();
        }
        compute(s);
        if (kc < 3) {
            cp_wait<0>();
            __syncthreads();
            convert_A(s ^ 1);
            __syncthreads();
            s ^= 1;
        }
    }

    const int g = lane >> 2, t4 = lane & 3;
#pragma unroll
    for (int mt = 0; mt < 2; mt++) {
        int r_lo = row0 + wm * 32 + mt * 16 + g;
        int r_hi = r_lo + 8;
        if (dis) {
            float dlo = dis[r_lo], dhi = dis[r_hi];
#pragma unroll
            for (int nt = 0; nt < 8; nt++) {
                int col = col0 + wn * 64 + nt * 8 + 2 * t4;
                __nv_bfloat162 lo = __floats2bfloat162_rn(acc[mt][nt][0] * dlo,
                                                          acc[mt][nt][1] * dlo);
                __nv_bfloat162 hi = __floats2bfloat162_rn(acc[mt][nt][2] * dhi,
                                                          acc[mt][nt][3] * dhi);
                *(__nv_bfloat162*)&Hs[(size_t)r_lo * HDIM + col] = lo;
                *(__nv_bfloat162*)&Hs[(size_t)r_hi * HDIM + col] = hi;
            }
        } else {
#pragma unroll
            for (int nt = 0; nt < 8; nt++) {
                int col = col0 + wn * 64 + nt * 8 + 2 * t4;
                *(float2*)&Cf[(size_t)r_lo * HDIM + col] =
                    make_float2(acc[mt][nt][0], acc[mt][nt][1]);
                *(float2*)&Cf[(size_t)r_hi * HDIM + col] =
                    make_float2(acc[mt][nt][2], acc[mt][nt][3]);
            }
        }
    }
}

// ---------------- sub gather: block = one contiguous 32-node subgraph ------------
// Accumulate relu(agg+b) in registers -> smem tree -> single fp32 store with
// fused mean divide. No atomics, no pool_finish pass, no pooled zeroing.
__global__ __launch_bounds__(256) void k_gather_sub(const float* __restrict__ bias)
{
    __shared__ float sh[8][HDIM];
    const int lane = threadIdx.x & 31, grp = threadIdx.x >> 5;
    const uint4* H = (const uint4*)g_hs_sub;
    float4 b0 = ((const float4*)bias)[lane * 2];
    float4 b1 = ((const float4*)bias)[lane * 2 + 1];
    float r0 = 0, r1 = 0, r2 = 0, r3 = 0, r4 = 0, r5 = 0, r6 = 0, r7 = 0;
    const int sseg = blockIdx.x;
#pragma unroll 1
    for (int it = 0; it < 4; it++) {
        int n = sseg * 32 + it * 8 + grp;
        int o0 = g_off_sub[n] >> 2, o1 = g_off_sub[n + 1] >> 2;
        uint4 a = H[(size_t)n * 32 + lane];
        __nv_bfloat162 A0 = *(__nv_bfloat162*)&a.x, A1 = *(__nv_bfloat162*)&a.y,
                       A2 = *(__nv_bfloat162*)&a.z, A3 = *(__nv_bfloat162*)&a.w;
#pragma unroll 1
        for (int k = o0; k < o1; k++) {
            int4 s4 = ((const int4*)g_csr_sub)[k];
            uint4 v;
            v = H[(size_t)s4.x * 32 + lane];
            A0 = badd2(A0, *(__nv_bfloat162*)&v.x); A1 = badd2(A1, *(__nv_bfloat162*)&v.y);
            A2 = badd2(A2, *(__nv_bfloat162*)&v.z); A3 = badd2(A3, *(__nv_bfloat162*)&v.w);
            v = H[(size_t)s4.y * 32 + lane];
            A0 = badd2(A0, *(__nv_bfloat162*)&v.x); A1 = badd2(A1, *(__nv_bfloat162*)&v.y);
            A2 = badd2(A2, *(__nv_bfloat162*)&v.z); A3 = badd2(A3, *(__nv_bfloat162*)&v.w);
            v = H[(size_t)s4.z * 32 + lane];
            A0 = badd2(A0, *(__nv_bfloat162*)&v.x); A1 = badd2(A1, *(__nv_bfloat162*)&v.y);
            A2 = badd2(A2, *(__nv_bfloat162*)&v.z); A3 = badd2(A3, *(__nv_bfloat162*)&v.w);
            v = H[(size_t)s4.w * 32 + lane];
            A0 = badd2(A0, *(__nv_bfloat162*)&v.x); A1 = badd2(A1, *(__nv_bfloat162*)&v.y);
            A2 = badd2(A2, *(__nv_bfloat162*)&v.z); A3 = badd2(A3, *(__nv_bfloat162*)&v.w);
        }
        float d = g_dis_sub[n];
        float2 f0 = __bfloat1622float2(A0), f1 = __bfloat1622float2(A1);
        float2 f2 = __bfloat1622float2(A2), f3 = __bfloat1622float2(A3);
        r0 += fmaxf(fmaf(f0.x, d, b0.x), 0.0f);
        r1 += fmaxf(fmaf(f0.y, d, b0.y), 0.0f);
        r2 += fmaxf(fmaf(f1.x, d, b0.z), 0.0f);
        r3 += fmaxf(fmaf(f1.y, d, b0.w), 0.0f);
        r4 += fmaxf(fmaf(f2.x, d, b1.x), 0.0f);
        r5 += fmaxf(fmaf(f2.y, d, b1.y), 0.0f);
        r6 += fmaxf(fmaf(f3.x, d, b1.z), 0.0f);
        r7 += fmaxf(fmaf(f3.y, d, b1.w), 0.0f);
    }
    float* row = sh[grp] + lane * 8;
    row[0] = r0; row[1] = r1; row[2] = r2; row[3] = r3;
    row[4] = r4; row[5] = r5; row[6] = r6; row[7] = r7;
    __syncthreads();
    int t = threadIdx.x;            // one dim per thread
    float s = 0.0f;
#pragma unroll
    for (int w = 0; w < 8; w++) s += sh[w][t];
    g_pooled[(size_t)sseg * HDIM + t] = s / fmaxf(g_cnt[sseg], 1.0f);
}

__global__ __launch_bounds__(256) void k_gather_glob(
    const int* __restrict__ batch, const float* __restrict__ bias)
{
    const int lane = threadIdx.x & 31, grp = threadIdx.x >> 5;
    const uint4* H = (const uint4*)g_hs_glob;
    float4 b0 = ((const float4*)bias)[lane * 2];
    float4 b1 = ((const float4*)bias)[lane * 2 + 1];
    float r0 = 0, r1 = 0, r2 = 0, r3 = 0, r4 = 0, r5 = 0, r6 = 0, r7 = 0;
    int cloc = 0;
#pragma unroll 1
    for (int it = 0; it < 4; it++) {
        int n = blockIdx.x * 32 + it * 8 + grp;
        int o0 = g_off_glob[n] >> 2, o1 = g_off_glob[n + 1] >> 2;
        uint4 a = H[(size_t)n * 32 + lane];
        __nv_bfloat162 A0 = *(__nv_bfloat162*)&a.x, A1 = *(__nv_bfloat162*)&a.y,
                       A2 = *(__nv_bfloat162*)&a.z, A3 = *(__nv_bfloat162*)&a.w;
#pragma unroll 1
        for (int k = o0; k < o1; k++) {
            int4 s4 = ((const int4*)g_csr_glob)[k];
            uint4 v;
            v = H[(size_t)s4.x * 32 + lane];
            A0 = badd2(A0, *(__nv_bfloat162*)&v.x); A1 = badd2(A1, *(__nv_bfloat162*)&v.y);
            A2 = badd2(A2, *(__nv_bfloat162*)&v.z); A3 = badd2(A3, *(__nv_bfloat162*)&v.w);
            v = H[(size_t)s4.y * 32 + lane];
            A0 = badd2(A0, *(__nv_bfloat162*)&v.x); A1 = badd2(A1, *(__nv_bfloat162*)&v.y);
            A2 = badd2(A2, *(__nv_bfloat162*)&v.z); A3 = badd2(A3, *(__nv_bfloat162*)&v.w);
            v = H[(size_t)s4.z * 32 + lane];
            A0 = badd2(A0, *(__nv_bfloat162*)&v.x); A1 = badd2(A1, *(__nv_bfloat162*)&v.y);
            A2 = badd2(A2, *(__nv_bfloat162*)&v.z); A3 = badd2(A3, *(__nv_bfloat162*)&v.w);
            v = H[(size_t)s4.w * 32 + lane];
            A0 = badd2(A0, *(__nv_bfloat162*)&v.x); A1 = badd2(A1, *(__nv_bfloat162*)&v.y);
            A2 = badd2(A2, *(__nv_bfloat162*)&v.z); A3 = badd2(A3, *(__nv_bfloat162*)&v.w);
        }
        if (batch[n] == 0) {
            float d = g_dis_glob[n];
            float2 f0 = __bfloat1622float2(A0), f1 = __bfloat1622float2(A1);
            float2 f2 = __bfloat1622float2(A2), f3 = __bfloat1622float2(A3);
            r0 += fmaxf(fmaf(f0.x, d, b0.x), 0.0f);
            r1 += fmaxf(fmaf(f0.y, d, b0.y), 0.0f);
            r2 += fmaxf(fmaf(f1.x, d, b0.z), 0.0f);
            r3 += fmaxf(fmaf(f1.y, d, b0.w), 0.0f);
            r4 += fmaxf(fmaf(f2.x, d, b1.x), 0.0f);
            r5 += fmaxf(fmaf(f2.y, d, b1.y), 0.0f);
            r6 += fmaxf(fmaf(f3.x, d, b1.z), 0.0f);
            r7 += fmaxf(fmaf(f3.y, d, b1.w), 0.0f);
            cloc++;
        }
    }
    float* dst = g_gemb_part + (size_t)(blockIdx.x & 63) * HDIM + lane * 8;
    red4(dst, r0, r1, r2, r3);
    red4(dst + 4, r4, r5, r6, r7);
    if (lane == 0) atomicAdd(&g_gcnt, cloc);
}

// ---------------- misc ----------------
__global__ void k_inject(const int* __restrict__ sub_index) {
    int idx = blockIdx.x * blockDim.x + threadIdx.x;
    if (idx >= SSEG * 128) return;
    int s = idx >> 7, c2 = idx & 127;
    int node = sub_index[s];
    float d = g_dis_glob[node];
    __nv_bfloat162* hp = (__nv_bfloat162*)g_hs_glob + (size_t)node * 128 + c2;
    float2 h = __bfloat1622float2(*hp);
    const float* p = g_p2 + (size_t)s * HDIM + c2 * 2;
    *hp = __floats2bfloat162_rn(fmaf(p[0], d, h.x), fmaf(p[1], d, h.y));
}
__global__ void k_final(const float* __restrict__ fc_W, const float* __restrict__ fc_b,
                        float* __restrict__ out) {
    __shared__ float sg[HDIM];
    int t = threadIdx.x;
    float s = 0.0f;
#pragma unroll 8
    for (int p = 0; p < 64; p++) s += g_gemb_part[p * HDIM + t];
    sg[t] = s / fmaxf((float)g_gcnt, 1.0f);
    __syncthreads();
    float acc = fc_b[t];
    const float* wr = fc_W + (size_t)t * HDIM;
#pragma unroll 8
    for (int h = 0; h < HDIM; h++) acc = fmaf(sg[h], wr[h], acc);
    out[t] = acc;
}

// ---------------- host launcher ----------------
extern "C" void kernel_launch(void* const* d_in, const int* in_sizes, int n_in,
                              void* d_out, int out_size) {
    const float* x_sub      = (const float*)d_in[0];
    const int*   ei_sub     = (const int*)  d_in[1];
    const int*   batch_sub  = (const int*)  d_in[2];
    const int*   sub_index  = (const int*)  d_in[3];
    const float* x_glob     = (const float*)d_in[4];
    const int*   ei_glob    = (const int*)  d_in[5];
    const int*   batch_glob = (const int*)  d_in[6];
    const float* W_sub      = (const float*)d_in[7];
    const float* b_sub      = (const float*)d_in[8];
    const float* W_glob     = (const float*)d_in[9];
    const float* b_glob     = (const float*)d_in[10];
    const float* fc_W       = (const float*)d_in[11];
    const float* fc_b       = (const float*)d_in[12];
    float* out = (float*)d_out;

    const int E_sub  = in_sizes[1] / 2;
    const int E_glob = in_sizes[5] / 2;

    static bool init = false;
    static float *p_dis_sub, *p_dis_glob, *p_pooled, *p_p2;
    static __nv_bfloat16 *pb_wt_sub, *pb_wt_glob, *p_hs_sub, *p_hs_glob;
    static cudaStream_t s2, s3;
    static cudaEvent_t eStart, eD, ePad, ePW, eG;
    if (!init) {
        init = true;
        cudaGetSymbolAddress((void**)&p_dis_sub,  g_dis_sub);
        cudaGetSymbolAddress((void**)&p_dis_glob, g_dis_glob);
        cudaGetSymbolAddress((void**)&p_pooled,   g_pooled);
        cudaGetSymbolAddress((void**)&p_p2,       g_p2);
        cudaGetSymbolAddress((void**)&pb_wt_sub,  g_bWt_sub);
        cudaGetSymbolAddress((void**)&pb_wt_glob, g_bWt_glob);
        cudaGetSymbolAddress((void**)&p_hs_sub,   g_hs_sub);
        cudaGetSymbolAddress((void**)&p_hs_glob,  g_hs_glob);
        cudaFuncSetAttribute(k_gemm_mma, cudaFuncAttributeMaxDynamicSharedMemorySize, GEMM_SMEM);
        cudaStreamCreateWithFlags(&s2, cudaStreamNonBlocking);
        cudaStreamCreateWithFlags(&s3, cudaStreamNonBlocking);
        cudaEventCreateWithFlags(&eStart, cudaEventDisableTiming);
        cudaEventCreateWithFlags(&eD,     cudaEventDisableTiming);
        cudaEventCreateWithFlags(&ePad,   cudaEventDisableTiming);
        cudaEventCreateWithFlags(&ePW,    cudaEventDisableTiming);
        cudaEventCreateWithFlags(&eG,     cudaEventDisableTiming);
    }

    const int total_hist = E_glob + E_sub + NSUB;

    // ---- fork ----
    cudaEventRecord(eStart, 0);
    cudaStreamWaitEvent(s2, eStart, 0);
    cudaStreamWaitEvent(s3, eStart, 0);

    // ---- s2: init + combined CSR build (both graphs) ----
    k_init<<<1024, 256, 0, s2>>>();
    k_hist_all<<<(total_hist + 255) / 256, 256, 0, s2>>>(ei_glob, E_glob, ei_sub, E_sub,
                                                         batch_sub);
    k_scan1_all<<<384, 256, 0, s2>>>();
    cudaEventRecord(eD, s2);
    k_scan2_all<<<2, 256, 0, s2>>>();
    k_scan3_all<<<384, 256, 0, s2>>>();
    k_fill_all<<<(E_glob + E_sub + 255) / 256, 256, 0, s2>>>(ei_glob, E_glob, ei_sub, E_sub);
    k_pad_all<<<384, 256, 0, s2>>>();
    cudaEventRecord(ePad, s2);

    // ---- s3: dual W pack + glob GEMM ----
    k_pack_Wt2<<<dim3(8, 8, 2), 256, 0, s3>>>(W_glob, W_sub);
    cudaEventRecord(ePW, s3);
    cudaStreamWaitEvent(s3, eD, 0);
    k_gemm_mma<<<dim3(NGLOB / 128, 2), 256, GEMM_SMEM, s3>>>(x_glob, pb_wt_glob,
                                                             p_hs_glob, nullptr, p_dis_glob);
    cudaEventRecord(eG, s3);

    // ---- s0: sub GEMM/gather + pooled GEMM + join tail ----
    cudaStreamWaitEvent(0, eD, 0);
    cudaStreamWaitEvent(0, ePW, 0);
    k_gemm_mma<<<dim3(NSUB / 128, 2), 256, GEMM_SMEM>>>(x_sub, pb_wt_sub,
                                                        p_hs_sub, nullptr, p_dis_sub);
    cudaStreamWaitEvent(0, ePad, 0);
    k_gather_sub<<<SSEG, 256>>>(b_sub);
    k_gemm_mma<<<dim3(SSEG / 128, 2), 256, GEMM_SMEM>>>(p_pooled, pb_wt_glob,
                                                        nullptr, p_p2, nullptr);

    cudaStreamWaitEvent(0, eG, 0);
    k_inject<<<(SSEG * 128 + 255) / 256, 256>>>(sub_index);
    k_gather_glob<<<NGLOB / 32, 256>>>(batch_glob, b_glob);
    k_final<<<1, 256>>>(fc_W, fc_b, out);
}